// round 8
// baseline (speedup 1.0000x reference)
#include <cuda_runtime.h>
#include <cuda_bf16.h>
#include <math.h>
#include <stdint.h>

#define Bsz  96
#define Hs   96
#define Ds   768
#define H2   9216
#define KQVN 27648

// ---------------- scratch (static device memory, no allocation) ----------------
__device__ float g_i[Bsz * Hs];
__device__ float g_f[Bsz * Hs];
__device__ float g_o[Bsz * H2];
__device__ float g_kqv[Bsz * KQVN];          // [96, 27648] : k | q | v (k pre-scaled by 1/96)
__device__ float g_vkT_part[16 * Hs * Hs];
__device__ float g_vkT[Hs * Hs];
__device__ int   g_denom[H2];                // float bits (exact, written by verify)
__device__ float g_max16[576 * H2];          // per-(16col-group, row) approx |max|, g-major
// pre-split bf16 operands
__device__ unsigned short g_AT[H2 * 192];    // n^T  [9216, 96hi|96lo]
__device__ unsigned short g_BT[H2 * 192];    // q^T
__device__ unsigned short g_npT[H2 * 192];   // n_prev^T
__device__ unsigned short g_kT[H2 * 192];    // k^T
__device__ unsigned short g_xs[Bsz * 1536];  // x split [96, 768hi|768lo]
__device__ unsigned short g_hps[Bsz * 192];  // h_prev split
__device__ unsigned short g_fis[Bsz * 384];  // [f hi|lo | i hi|lo]
__device__ unsigned short g_Cs[Bsz * 192];   // C split

// ---------------- helpers ----------------
__device__ __forceinline__ uint32_t smem_u32(const void* p) {
    uint32_t a;
    asm("{ .reg .u64 t; cvta.to.shared.u64 t, %1; cvt.u32.u64 %0, t; }" : "=r"(a) : "l"(p));
    return a;
}
#define LDSM_X4(r0, r1, r2, r3, addr) \
    asm volatile("ldmatrix.sync.aligned.m8n8.x4.shared.b16 {%0,%1,%2,%3}, [%4];" \
                 : "=r"(r0), "=r"(r1), "=r"(r2), "=r"(r3) : "r"(addr))
#define MMA16816(d, a, b0, b1) \
    asm volatile("mma.sync.aligned.m16n8k16.row.col.f32.bf16.bf16.f32 " \
                 "{%0,%1,%2,%3},{%4,%5,%6,%7},{%8,%9},{%0,%1,%2,%3};" \
                 : "+f"((d)[0]), "+f"((d)[1]), "+f"((d)[2]), "+f"((d)[3]) \
                 : "r"((a)[0]), "r"((a)[1]), "r"((a)[2]), "r"((a)[3]), "r"(b0), "r"(b1))

// ---------------- misc splits, one launch ----------------
__global__ __launch_bounds__(256)
void split_misc(const float* __restrict__ x, const float* __restrict__ hp,
                unsigned short* __restrict__ xs_u16, unsigned short* __restrict__ hps_u16) {
    int blk = blockIdx.x, tid = threadIdx.x;
    if (blk < 288) {                      // x split: 96x768
        __nv_bfloat16* xs = (__nv_bfloat16*)xs_u16;
        int e = blk * 256 + tid;
        int r = e / Ds, c = e % Ds;
        float v = x[e];
        __nv_bfloat16 hi = __float2bfloat16(v);
        xs[(size_t)r * 1536 + c] = hi;
        xs[(size_t)r * 1536 + Ds + c] = __float2bfloat16(v - __bfloat162float(hi));
    } else {                              // h_prev split: 96x96
        __nv_bfloat16* hs = (__nv_bfloat16*)hps_u16;
        int e = (blk - 288) * 256 + tid;
        int r = e / Hs, c = e % Hs;
        float v = hp[e];
        __nv_bfloat16 hi = __float2bfloat16(v);
        hs[(size_t)r * 192 + c] = hi;
        hs[(size_t)r * 192 + Hs + c] = __float2bfloat16(v - __bfloat162float(hi));
    }
}

// ---------------- fast transpose+split: dst[r][j]=hi(src[j][r]), dst[r][96+j]=lo ----
__global__ __launch_bounds__(256)
void prep_splitT(const float* __restrict__ src, int ld,
                 unsigned short* __restrict__ dst_u16) {
    __nv_bfloat16* dst = (__nv_bfloat16*)dst_u16;
    __shared__ float t[32][68];
    int r0 = blockIdx.x * 64, j0 = blockIdx.y * 32, tid = threadIdx.x;
#pragma unroll
    for (int it = 0; it < 2; it++) {
        int e = tid + it * 256;
        int jj = e >> 4, c4 = (e & 15) * 4;
        float4 v = *(const float4*)(src + (size_t)(j0 + jj) * ld + r0 + c4);
        *(float4*)&t[jj][c4] = v;
    }
    __syncthreads();
#pragma unroll
    for (int it = 0; it < 2; it++) {
        int e = tid + it * 256;
        int rr = e >> 3, q = e & 7;
        int isLo = q >> 2, jb = (q & 3) * 8;
        __nv_bfloat16 vals[8];
#pragma unroll
        for (int w = 0; w < 8; w++) {
            float f = t[jb + w][rr];
            __nv_bfloat16 hi = __float2bfloat16(f);
            vals[w] = isLo ? __float2bfloat16(f - __bfloat162float(hi)) : hi;
        }
        *(uint4*)(dst + (size_t)(r0 + rr) * 192 + isLo * 96 + j0 + jb) = *(uint4*)vals;
    }
}

// ---------------- gates: i = exp(x wix^T + b), f = exp(hp wfx^T + b), + split ----
__global__ __launch_bounds__(256)
void gates_kernel(const float* __restrict__ x, const float* __restrict__ hp,
                  const float* __restrict__ wix_w, const float* __restrict__ wix_b,
                  const float* __restrict__ wfx_w, const float* __restrict__ wfx_b,
                  float* __restrict__ gi, float* __restrict__ gf,
                  unsigned short* __restrict__ fis_u16) {
    int gw = blockIdx.x * 8 + (threadIdx.x >> 5);
    int lane = threadIdx.x & 31;
    int isI = gw < Bsz * Hs;
    int o = isI ? gw : gw - Bsz * Hs;
    int b = o / Hs, n = o % Hs;
    const float* a = isI ? x + (size_t)b * Ds : hp + (size_t)b * Hs;
    const float* w = isI ? wix_w + (size_t)n * Ds : wfx_w + (size_t)n * Hs;
    int K = isI ? Ds : Hs;
    float acc = 0.f;
    for (int k = lane; k < K; k += 32) acc += a[k] * w[k];
#pragma unroll
    for (int off = 16; off; off >>= 1) acc += __shfl_xor_sync(0xffffffffu, acc, off);
    if (lane == 0) {
        float v = expf(acc + (isI ? wix_b[n] : wfx_b[n]));
        (isI ? gi : gf)[o] = v;
        __nv_bfloat16* fis = (__nv_bfloat16*)fis_u16;
        __nv_bfloat16 hi = __float2bfloat16(v);
        int base = b * 384 + (isI ? 192 : 0) + n;
        fis[base] = hi;
        fis[base + 96] = __float2bfloat16(v - __bfloat162float(hi));
    }
}

// ======== Variant A: HMMA NT GEMM (N-tile 64, occ 3), B fp32 converted on the fly ====
// EPI 0: kqv (bias + scale k) + fused kT/qT transpose-split epilogue
// EPI 1: sigmoid(bias)
template <int EPI, int KTOT>
__global__ __launch_bounds__(256, 3)
void hmma_convA(const unsigned short* __restrict__ Asp_u16,
                const float* __restrict__ Bm,
                const float* __restrict__ bias,
                float* __restrict__ out, int ldo,
                unsigned short* __restrict__ kT_u16,
                unsigned short* __restrict__ qT_u16) {
    const __nv_bfloat16* Asp = (const __nv_bfloat16*)Asp_u16;
    extern __shared__ __nv_bfloat16 dyn[];
    __nv_bfloat16* sAr = dyn;                        // [96][72]
    __nv_bfloat16* sBr = dyn + 96 * 72;              // [64][72]
    __nv_bfloat16* sT  = dyn + 96 * 72 + 64 * 72;    // [64][192] (EPI 0 only)
    int tid = threadIdx.x, warp = tid >> 5, lane = tid & 31;
    int n0 = blockIdx.x * 64;
    int wm = warp & 1, wn = warp >> 1;
    float acc[3][2][4] = {};

    uint4 aPre[3];
    float4 bPre[2];
    const int NC = KTOT / 32;

#pragma unroll 1
    for (int c = 0; c < NC; c++) {
        if (c == 0) {
#pragma unroll
            for (int t = 0; t < 3; t++) {
                int e = tid + t * 256;
                int r = e >> 3, col = (e & 7) * 8;
                int sc = (col < 32) ? col : (KTOT + col - 32);
                aPre[t] = *(const uint4*)(Asp + (size_t)r * (2 * KTOT) + sc);
            }
#pragma unroll
            for (int t = 0; t < 2; t++) {
                int e = tid + t * 256;
                int r = e >> 3, g = e & 7;
                bPre[t] = *(const float4*)(Bm + (size_t)(n0 + r) * KTOT + g * 4);
            }
        }
        __syncthreads();
#pragma unroll
        for (int t = 0; t < 3; t++) {
            int e = tid + t * 256;
            int r = e >> 3, col = (e & 7) * 8;
            *(uint4*)&sAr[r * 72 + col] = aPre[t];
        }
#pragma unroll
        for (int t = 0; t < 2; t++) {
            int e = tid + t * 256;
            int r = e >> 3, g = e & 7;
            float vv[4] = {bPre[t].x, bPre[t].y, bPre[t].z, bPre[t].w};
#pragma unroll
            for (int j = 0; j < 4; j++) {
                __nv_bfloat16 hi = __float2bfloat16(vv[j]);
                sBr[r * 72 + g * 4 + j] = hi;
                sBr[r * 72 + 32 + g * 4 + j] = __float2bfloat16(vv[j] - __bfloat162float(hi));
            }
        }
        __syncthreads();
        if (c + 1 < NC) {
            int k0 = (c + 1) * 32;
#pragma unroll
            for (int t = 0; t < 3; t++) {
                int e = tid + t * 256;
                int r = e >> 3, col = (e & 7) * 8;
                int sc = (col < 32) ? (k0 + col) : (KTOT + k0 + col - 32);
                aPre[t] = *(const uint4*)(Asp + (size_t)r * (2 * KTOT) + sc);
            }
#pragma unroll
            for (int t = 0; t < 2; t++) {
                int e = tid + t * 256;
                int r = e >> 3, g = e & 7;
                bPre[t] = *(const float4*)(Bm + (size_t)(n0 + r) * KTOT + k0 + g * 4);
            }
        }
        uint32_t aBase = smem_u32(sAr);
        uint32_t bBase = smem_u32(sBr);
        int aRow = wm * 48 + (lane & 15);
        int aCol = (lane >> 4) << 3;
        int bRow = wn * 16 + (lane & 7) + ((lane >> 4) << 3);
        int bCol = ((lane >> 3) & 1) << 3;
        // merged passes: A_hi x (B_hi, B_lo)
#pragma unroll
        for (int ks = 0; ks < 2; ks++) {
            int ka = ks * 16 + aCol, kb = ks * 16 + bCol;
            uint32_t af[3][4], bh[4], bl[4];
#pragma unroll
            for (int mi = 0; mi < 3; mi++) {
                uint32_t addr = aBase + (uint32_t)(((aRow + mi * 16) * 72 + ka) * 2);
                LDSM_X4(af[mi][0], af[mi][1], af[mi][2], af[mi][3], addr);
            }
            {
                uint32_t addr = bBase + (uint32_t)((bRow * 72 + kb) * 2);
                LDSM_X4(bh[0], bh[1], bh[2], bh[3], addr);
                addr = bBase + (uint32_t)((bRow * 72 + kb + 32) * 2);
                LDSM_X4(bl[0], bl[1], bl[2], bl[3], addr);
            }
#pragma unroll
            for (int mi = 0; mi < 3; mi++)
#pragma unroll
                for (int nj = 0; nj < 2; nj++) {
                    MMA16816(acc[mi][nj], af[mi], bh[nj * 2], bh[nj * 2 + 1]);
                    MMA16816(acc[mi][nj], af[mi], bl[nj * 2], bl[nj * 2 + 1]);
                }
        }
        // pass 2: A_lo x B_hi
#pragma unroll
        for (int ks = 0; ks < 2; ks++) {
            int ka = 32 + ks * 16 + aCol, kb = ks * 16 + bCol;
            uint32_t af[3][4], bh[4];
#pragma unroll
            for (int mi = 0; mi < 3; mi++) {
                uint32_t addr = aBase + (uint32_t)(((aRow + mi * 16) * 72 + ka) * 2);
                LDSM_X4(af[mi][0], af[mi][1], af[mi][2], af[mi][3], addr);
            }
            {
                uint32_t addr = bBase + (uint32_t)((bRow * 72 + kb) * 2);
                LDSM_X4(bh[0], bh[1], bh[2], bh[3], addr);
            }
#pragma unroll
            for (int mi = 0; mi < 3; mi++)
#pragma unroll
                for (int nj = 0; nj < 2; nj++)
                    MMA16816(acc[mi][nj], af[mi], bh[nj * 2], bh[nj * 2 + 1]);
        }
    }
    const bool doT = (EPI == 0) && (n0 < 2 * H2);
#pragma unroll
    for (int mi = 0; mi < 3; mi++)
#pragma unroll
        for (int nj = 0; nj < 2; nj++)
#pragma unroll
            for (int r = 0; r < 4; r++) {
                int m = wm * 48 + mi * 16 + (lane >> 2) + ((r >> 1) * 8);
                int gl = wn * 16 + nj * 8 + (lane & 3) * 2 + (r & 1);
                int gn = n0 + gl;
                float v = acc[mi][nj][r] + bias[gn];
                if (EPI == 0) { if (gn < H2) v *= (1.0f / 96.0f); }
                if (EPI == 1) v = 1.0f / (1.0f + expf(-v));
                out[(size_t)m * ldo + gn] = v;
                if (doT) {
                    __nv_bfloat16 hi = __float2bfloat16(v);
                    sT[gl * 192 + m] = hi;
                    sT[gl * 192 + 96 + m] = __float2bfloat16(v - __bfloat162float(hi));
                }
            }
    if (doT) {
        __syncthreads();
        __nv_bfloat16* dstT = (__nv_bfloat16*)((n0 < H2) ? kT_u16 : qT_u16);
        int cb = (n0 < H2) ? n0 : (n0 - H2);
        for (int e = tid; e < 64 * 24; e += 256) {
            int row = e / 24, g = e % 24;
            *(uint4*)(dstT + (size_t)(cb + row) * 192 + g * 8) = *(uint4*)(sT + row * 192 + g * 8);
        }
    }
}

// ======== Variant B: HMMA NT GEMM, pre-split bf16 B [N, 192], up to 2 K-segments ====
// EPI 2: n (+ fused AT transpose-split), EPI 3: h = o * acc / denom
template <int EPI>
__global__ __launch_bounds__(256, 2)
void hmma_preB(const unsigned short* __restrict__ Asp_u16, int lda,
               const unsigned short* __restrict__ B1_u16,
               const unsigned short* __restrict__ B2_u16,
               int nseg,
               const float* __restrict__ omat,
               const int* __restrict__ denomBits,
               float* __restrict__ out, int ldo,
               unsigned short* __restrict__ AT_u16) {
    const __nv_bfloat16* Asp = (const __nv_bfloat16*)Asp_u16;
    extern __shared__ __nv_bfloat16 dsm[];
    __nv_bfloat16* sA = dsm;             // [96][200]
    __nv_bfloat16* sB = dsm + 96 * 200;  // [64][200]
    int tid = threadIdx.x, warp = tid >> 5, lane = tid & 31;
    int n0 = blockIdx.x * 64;
    int wm = warp & 1, wn = warp >> 1;
    float acc[3][2][4] = {};

#pragma unroll 1
    for (int s = 0; s < nseg; s++) {
        const __nv_bfloat16* Bseg =
            (s == 0) ? (const __nv_bfloat16*)B1_u16 : (const __nv_bfloat16*)B2_u16;
        __syncthreads();
        for (int e = tid; e < 96 * 24; e += 256) {
            int r = e / 24, g = e % 24;
            *(uint4*)(sA + r * 200 + g * 8) =
                *(const uint4*)(Asp + (size_t)r * lda + s * 192 + g * 8);
        }
        for (int e = tid; e < 64 * 24; e += 256) {
            int r = e / 24, g = e % 24;
            *(uint4*)(sB + r * 200 + g * 8) =
                *(const uint4*)(Bseg + (size_t)(n0 + r) * 192 + g * 8);
        }
        __syncthreads();
        uint32_t aBase = smem_u32(sA), bBase = smem_u32(sB);
        int aRow = wm * 48 + (lane & 15), aCol = (lane >> 4) << 3;
        int bRow = wn * 16 + (lane & 7) + ((lane >> 4) << 3);
        int bCol = ((lane >> 3) & 1) << 3;
        // merged passes: A_hi x (B_hi, B_lo)
#pragma unroll
        for (int ks = 0; ks < 6; ks++) {
            int ka = ks * 16 + aCol, kb = ks * 16 + bCol;
            uint32_t af[3][4], bh[4], bl[4];
#pragma unroll
            for (int mi = 0; mi < 3; mi++) {
                uint32_t addr = aBase + (uint32_t)(((aRow + mi * 16) * 200 + ka) * 2);
                LDSM_X4(af[mi][0], af[mi][1], af[mi][2], af[mi][3], addr);
            }
            {
                uint32_t addr = bBase + (uint32_t)((bRow * 200 + kb) * 2);
                LDSM_X4(bh[0], bh[1], bh[2], bh[3], addr);
                addr = bBase + (uint32_t)((bRow * 200 + kb + 96) * 2);
                LDSM_X4(bl[0], bl[1], bl[2], bl[3], addr);
            }
#pragma unroll
            for (int mi = 0; mi < 3; mi++)
#pragma unroll
                for (int nj = 0; nj < 2; nj++) {
                    MMA16816(acc[mi][nj], af[mi], bh[nj * 2], bh[nj * 2 + 1]);
                    MMA16816(acc[mi][nj], af[mi], bl[nj * 2], bl[nj * 2 + 1]);
                }
        }
        // pass 2: A_lo x B_hi
#pragma unroll
        for (int ks = 0; ks < 6; ks++) {
            int ka = 96 + ks * 16 + aCol, kb = ks * 16 + bCol;
            uint32_t af[3][4], bh[4];
#pragma unroll
            for (int mi = 0; mi < 3; mi++) {
                uint32_t addr = aBase + (uint32_t)(((aRow + mi * 16) * 200 + ka) * 2);
                LDSM_X4(af[mi][0], af[mi][1], af[mi][2], af[mi][3], addr);
            }
            {
                uint32_t addr = bBase + (uint32_t)((bRow * 200 + kb) * 2);
                LDSM_X4(bh[0], bh[1], bh[2], bh[3], addr);
            }
#pragma unroll
            for (int mi = 0; mi < 3; mi++)
#pragma unroll
                for (int nj = 0; nj < 2; nj++)
                    MMA16816(acc[mi][nj], af[mi], bh[nj * 2], bh[nj * 2 + 1]);
        }
    }
    if (EPI == 2) __syncthreads();   // before reusing sA as staging
#pragma unroll
    for (int mi = 0; mi < 3; mi++)
#pragma unroll
        for (int nj = 0; nj < 2; nj++)
#pragma unroll
            for (int r = 0; r < 4; r++) {
                int m = wm * 48 + mi * 16 + (lane >> 2) + ((r >> 1) * 8);
                int gl = wn * 16 + nj * 8 + (lane & 3) * 2 + (r & 1);
                int gn = n0 + gl;
                float v = acc[mi][nj][r];
                if (EPI == 3)
                    v = omat[(size_t)m * H2 + gn] * v / __int_as_float(denomBits[gn]);
                out[(size_t)m * ldo + gn] = v;
                if (EPI == 2) {
                    __nv_bfloat16 hi = __float2bfloat16(v);
                    sA[gl * 192 + m] = hi;
                    sA[gl * 192 + 96 + m] = __float2bfloat16(v - __bfloat162float(hi));
                }
            }
    if (EPI == 2) {
        __syncthreads();
        __nv_bfloat16* AT = (__nv_bfloat16*)AT_u16;
        for (int e = tid; e < 64 * 24; e += 256) {
            int row = e / 24, g = e % 24;
            *(uint4*)(AT + (size_t)(n0 + row) * 192 + g * 8) = *(uint4*)(sA + row * 192 + g * 8);
        }
    }
}

// ================= denom phase 1: single hi-pass screen =================
// gmax16[(by*8 + wn*2 + g) * H2 + r] = max |approx| over that 16-col group
#define SMP 104

__global__ __launch_bounds__(256, 2)
void denom_p1_kernel(const unsigned short* __restrict__ AT,
                     const unsigned short* __restrict__ BT,
                     float* __restrict__ gmax16) {
    extern __shared__ __align__(16) unsigned short sm[];
    unsigned short* sA = sm;
    unsigned short* sB = sm + 128 * SMP;
    int tid = threadIdx.x;
    int r0 = blockIdx.x * 128, c0 = blockIdx.y * 128;

    for (int e = tid; e < 128 * 12; e += 256) {
        int row = e / 12, c8 = (e % 12) * 8;
        *(float4*)(sA + row * SMP + c8) = *(const float4*)(AT + (size_t)(r0 + row) * 192 + c8);
        *(float4*)(sB + row * SMP + c8) = *(const float4*)(BT + (size_t)(c0 + row) * 192 + c8);
    }
    __syncthreads();

    int warp = tid >> 5, lane = tid & 31;
    int wm = warp & 1, wn = warp >> 1;
    uint32_t aBase = smem_u32(sA);
    uint32_t bBase = smem_u32(sB);

    float acc[4][4][4];
#pragma unroll
    for (int mi = 0; mi < 4; mi++)
#pragma unroll
        for (int nj = 0; nj < 4; nj++)
#pragma unroll
            for (int r = 0; r < 4; r++) acc[mi][nj][r] = 0.f;

    int aRow = wm * 64 + (lane & 15);
    int aColL = (lane >> 4) << 3;
    int bRow = wn * 32 + (lane & 7) + ((lane >> 4) << 3);
    int bColL = ((lane >> 3) & 1) << 3;

#pragma unroll 1
    for (int ks = 0; ks < 6; ks++) {
        int ka = ks * 16 + aColL;
        int kb = ks * 16 + bColL;
        uint32_t af[4][4], bh[2][4];
#pragma unroll
        for (int mi = 0; mi < 4; mi++) {
            uint32_t addr = aBase + (uint32_t)(((aRow + mi * 16) * SMP + ka) * 2);
            LDSM_X4(af[mi][0], af[mi][1], af[mi][2], af[mi][3], addr);
        }
#pragma unroll
        for (int nj2 = 0; nj2 < 2; nj2++) {
            uint32_t addr = bBase + (uint32_t)(((bRow + nj2 * 16) * SMP + kb) * 2);
            LDSM_X4(bh[nj2][0], bh[nj2][1], bh[nj2][2], bh[nj2][3], addr);
        }
#pragma unroll
        for (int mi = 0; mi < 4; mi++)
#pragma unroll
            for (int nj = 0; nj < 4; nj++)
                MMA16816(acc[mi][nj], af[mi], bh[nj >> 1][(nj & 1) * 2],
                         bh[nj >> 1][(nj & 1) * 2 + 1]);
    }

    // epilogue: per (row, 16-col group) max; each value produced by one quad
#pragma unroll
    for (int mi = 0; mi < 4; mi++) {
        float g0a = fmaxf(fmaxf(fabsf(acc[mi][0][0]), fabsf(acc[mi][0][1])),
                          fmaxf(fabsf(acc[mi][1][0]), fabsf(acc[mi][1][1])));
        float g0b = fmaxf(fmaxf(fabsf(acc[mi][0][2]), fabsf(acc[mi][0][3])),
                          fmaxf(fabsf(acc[mi][1][2]), fabsf(acc[mi][1][3])));
        float g1a = fmaxf(fmaxf(fabsf(acc[mi][2][0]), fabsf(acc[mi][2][1])),
                          fmaxf(fabsf(acc[mi][3][0]), fabsf(acc[mi][3][1])));
        float g1b = fmaxf(fmaxf(fabsf(acc[mi][2][2]), fabsf(acc[mi][2][3])),
                          fmaxf(fabsf(acc[mi][3][2]), fabsf(acc[mi][3][3])));
#pragma unroll
        for (int off = 1; off <= 2; off <<= 1) {
            g0a = fmaxf(g0a, __shfl_xor_sync(0xffffffffu, g0a, off));
            g0b = fmaxf(g0b, __shfl_xor_sync(0xffffffffu, g0b, off));
            g1a = fmaxf(g1a, __shfl_xor_sync(0xffffffffu, g1a, off));
            g1b = fmaxf(g1b, __shfl_xor_sync(0xffffffffu, g1b, off));
        }
        if ((lane & 3) == 0) {
            int rr = r0 + wm * 64 + mi * 16 + (lane >> 2);
            size_t gb = (size_t)(blockIdx.y * 8 + wn * 2);
            gmax16[gb * H2 + rr]           = g0a;
            gmax16[gb * H2 + rr + 8]       = g0b;
            gmax16[(gb + 1) * H2 + rr]     = g1a;
            gmax16[(gb + 1) * H2 + rr + 8] = g1b;
        }
    }
}

// ================= denom phase 2: exact verify of flagged groups =================
// warp w owns rows w*32 .. w*32+31 (lane = row). thresh = 0.96 * approx rowmax.
__global__ __launch_bounds__(256)
void denom_verify(const float* __restrict__ gmax16,
                  const float* __restrict__ nmat,   // out_n [96, 9216]
                  const float* __restrict__ kqv,    // q at + H2, ld = KQVN
                  int* __restrict__ denomBits) {
    int w = (blockIdx.x * 256 + threadIdx.x) >> 5;   // 0..287
    int lane = threadIdx.x & 31;
    int myr = w * 32 + lane;
    const float* q = kqv + H2;

    float rmax = 0.f;
    for (int g = 0; g < 576; g++)
        rmax = fmaxf(rmax, gmax16[(size_t)g * H2 + myr]);
    float thresh = 0.96f * rmax;

    float best = 0.f;
    for (int g = 0; g < 576; g++) {
        float v = gmax16[(size_t)g * H2 + myr];
        unsigned mask = __ballot_sync(0xffffffffu, v >= thresh);
        while (mask) {
            int s = __ffs(mask) - 1;
            mask &= mask - 1;
            int row = w * 32 + s;
            // exact fp32: 16 cols of group g, lanes 0-15 = cols, lane>>4 = b-half
            int c = g * 16 + (lane & 15);
            int b0 = (lane >> 4) * 48;
            float acc = 0.f;
#pragma unroll 4
            for (int b = 0; b < 48; b++) {
                float nv = __ldg(&nmat[(size_t)(b0 + b) * H2 + row]);
                acc += nv * __ldg(&q[(size_t)(b0 + b) * KQVN + c]);
            }
            acc += __shfl_xor_sync(0xffffffffu, acc, 16);
            float a = fabsf(acc);
#pragma unroll
            for (int off = 8; off; off >>= 1)
                a = fmaxf(a, __shfl_xor_sync(0xffffffffu, a, off));
            if (lane == s) best = fmaxf(best, a);
        }
    }
    denomBits[myr] = __float_as_int(best);
}

// ---------------- v @ k^T : deterministic split-K (16 chunks of 576) ----------------
__global__ __launch_bounds__(256)
void vkt_part_kernel(const float* __restrict__ kqv, float* __restrict__ part) {
    const float* V  = kqv + 2 * H2;
    const float* Km = kqv;
    __shared__ float As[32][17];
    __shared__ float Bs[32][17];
    int tid = threadIdx.x, tx = tid & 15, ty = tid >> 4;
    int m0 = blockIdx.x * 32, n0 = blockIdx.y * 32;
    int kbase = blockIdx.z * 576;
    float a00 = 0, a01 = 0, a10 = 0, a11 = 0;
    for (int k0 = 0; k0 < 576; k0 += 16) {
        for (int e = tid; e < 32 * 16; e += 256) {
            int m = e >> 4, k = e & 15;
            As[m][k] = V[(size_t)(m0 + m) * KQVN + kbase + k0 + k];
            Bs[m][k] = Km[(size_t)(n0 + m) * KQVN + kbase + k0 + k];
        }
        __syncthreads();
#pragma unroll
        for (int kk = 0; kk < 16; kk++) {
            float av0 = As[ty][kk],      av1 = As[ty + 16][kk];
            float bv0 = Bs[tx][kk],      bv1 = Bs[tx + 16][kk];
            a00 += av0 * bv0; a01 += av0 * bv1;
            a10 += av1 * bv0; a11 += av1 * bv1;
        }
        __syncthreads();
    }
    float* p = part + blockIdx.z * (Hs * Hs);
    p[(m0 + ty) * Hs + (n0 + tx)]           = a00;
    p[(m0 + ty) * Hs + (n0 + tx + 16)]      = a01;
    p[(m0 + ty + 16) * Hs + (n0 + tx)]      = a10;
    p[(m0 + ty + 16) * Hs + (n0 + tx + 16)] = a11;
}

__global__ void vkt_reduce_kernel(const float* __restrict__ part, float* __restrict__ vkt) {
    int idx = blockIdx.x * blockDim.x + threadIdx.x;
    if (idx < Hs * Hs) {
        float s = 0.f;
#pragma unroll
        for (int c = 0; c < 16; c++) s += part[c * (Hs * Hs) + idx];
        vkt[idx] = s;
    }
}

// ---------------- C = f @ C_prev + i @ vkT   (96x96), + split ----------------
__global__ void c_kernel(const float* __restrict__ f, const float* __restrict__ i_,
                         const float* __restrict__ C_prev, const float* __restrict__ vkt,
                         float* __restrict__ outC, unsigned short* __restrict__ Cs_u16) {
    __shared__ float fs[Hs], is[Hs];
    int b = blockIdx.x, n = threadIdx.x;
    fs[n] = f[b * Hs + n];
    is[n] = i_[b * Hs + n];
    __syncthreads();
    float acc = 0.f;
    for (int h = 0; h < Hs; h++)
        acc += fs[h] * C_prev[h * Hs + n] + is[h] * vkt[h * Hs + n];
    outC[b * Hs + n] = acc;
    __nv_bfloat16* Cs = (__nv_bfloat16*)Cs_u16;
    __nv_bfloat16 hi = __float2bfloat16(acc);
    Cs[b * 192 + n] = hi;
    Cs[b * 192 + 96 + n] = __float2bfloat16(acc - __bfloat162float(hi));
}

// ---------------- launch ----------------
extern "C" void kernel_launch(void* const* d_in, const int* in_sizes, int n_in,
                              void* d_out, int out_size) {
    const float* x      = (const float*)d_in[0];
    const float* h_prev = (const float*)d_in[1];
    const float* C_prev = (const float*)d_in[2];
    const float* n_prev = (const float*)d_in[3];
    const float* wix_w  = (const float*)d_in[4];
    const float* wix_b  = (const float*)d_in[5];
    const float* wfx_w  = (const float*)d_in[6];
    const float* wfx_b  = (const float*)d_in[7];
    const float* Wox_w  = (const float*)d_in[8];
    const float* Wox_b  = (const float*)d_in[9];
    const float* Wkqv_w = (const float*)d_in[10];
    const float* Wkqv_b = (const float*)d_in[11];

    float* out   = (float*)d_out;
    float* out_h = out;                       // [96, 9216]
    float* out_C = out + Bsz * H2;            // [96, 96]
    float* out_n = out_C + Bsz * Hs;          // [96, 9216]

    float *p_i, *p_f, *p_o, *p_kqv, *p_part, *p_vkt, *p_gmax;
    int* p_denom;
    unsigned short *p_AT, *p_BT, *p_npT, *p_kT, *p_xs, *p_hps, *p_fis, *p_Cs;
    cudaGetSymbolAddress((void**)&p_i,     g_i);
    cudaGetSymbolAddress((void**)&p_f,     g_f);
    cudaGetSymbolAddress((void**)&p_o,     g_o);
    cudaGetSymbolAddress((void**)&p_kqv,   g_kqv);
    cudaGetSymbolAddress((void**)&p_part,  g_vkT_part);
    cudaGetSymbolAddress((void**)&p_vkt,   g_vkT);
    cudaGetSymbolAddress((void**)&p_denom, g_denom);
    cudaGetSymbolAddress((void**)&p_gmax,  g_max16);
    cudaGetSymbolAddress((void**)&p_AT,    g_AT);
    cudaGetSymbolAddress((void**)&p_BT,    g_BT);
    cudaGetSymbolAddress((void**)&p_npT,   g_npT);
    cudaGetSymbolAddress((void**)&p_kT,    g_kT);
    cudaGetSymbolAddress((void**)&p_xs,    g_xs);
    cudaGetSymbolAddress((void**)&p_hps,   g_hps);
    cudaGetSymbolAddress((void**)&p_fis,   g_fis);
    cudaGetSymbolAddress((void**)&p_Cs,    g_Cs);

    const int P1_SMEM    = 2 * 128 * SMP * 2;      // 53248
    const int PREB_SMEM  = (96 + 64) * 200 * 2;    // 64000
    const int CONV_SMEM  = (96 * 72 + 64 * 72 + 64 * 192) * 2;   // 47616
    const int CONV1_SMEM = (96 * 72 + 64 * 72) * 2;              // 23040
    cudaFuncSetAttribute(denom_p1_kernel,
                         cudaFuncAttributeMaxDynamicSharedMemorySize, P1_SMEM);
    cudaFuncSetAttribute(hmma_preB<2>,
                         cudaFuncAttributeMaxDynamicSharedMemorySize, PREB_SMEM);
    cudaFuncSetAttribute(hmma_preB<3>,
                         cudaFuncAttributeMaxDynamicSharedMemorySize, PREB_SMEM);
    cudaFuncSetAttribute(hmma_convA<0, Ds>,
                         cudaFuncAttributeMaxDynamicSharedMemorySize, CONV_SMEM);
    cudaFuncSetAttribute(hmma_convA<1, Hs>,
                         cudaFuncAttributeMaxDynamicSharedMemorySize, CONV1_SMEM);

    // x/h_prev splits
    split_misc<<<324, 256>>>(x, h_prev, p_xs, p_hps);

    // n_prev^T split
    prep_splitT<<<dim3(H2 / 64, 3), 256>>>(n_prev, H2, p_npT);

    // i, f gates + split
    gates_kernel<<<2304, 256>>>(x, h_prev, wix_w, wix_b, wfx_w, wfx_b, p_i, p_f, p_fis);

    // kqv = x @ Wkqv^T + b (HMMA) + fused kT/qT transpose-splits
    hmma_convA<0, Ds><<<KQVN / 64, 256, CONV_SMEM>>>(p_xs, Wkqv_w, Wkqv_b, p_kqv, KQVN,
                                                     p_kT, p_BT);

    // o = sigmoid(h_prev @ Wox^T + b)
    hmma_convA<1, Hs><<<H2 / 64, 256, CONV1_SMEM>>>(p_hps, Wox_w, Wox_b, p_o, H2,
                                                    nullptr, nullptr);

    // n = f @ n_prev + i @ k  (HMMA) + fused AT transpose-split
    hmma_preB<2><<<H2 / 64, 256, PREB_SMEM>>>(p_fis, 384, p_npT, p_kT, 2,
                                              nullptr, nullptr, out_n, H2, p_AT);

    // vkT = v @ k^T
    vkt_part_kernel<<<dim3(3, 3, 16), 256>>>(p_kqv, p_part);
    vkt_reduce_kernel<<<36, 256>>>(p_part, p_vkt);

    // C = f @ C_prev + i @ vkT (+ split)
    c_kernel<<<Bsz, Hs>>>(p_f, p_i, C_prev, p_vkt, out_C, p_Cs);

    // denom: phase 1 screen (hi-only), phase 2 exact verify
    denom_p1_kernel<<<dim3(72, 72), 256, P1_SMEM>>>(p_AT, p_BT, p_gmax);
    denom_verify<<<36, 256>>>(p_gmax, out_n, p_kqv, p_denom);

    // h = o * (C @ q) / denom
    hmma_preB<3><<<H2 / 64, 256, PREB_SMEM>>>(p_Cs, 192, p_BT, nullptr, 1,
                                              p_o, p_denom, out_h, H2, nullptr);
}

// round 9
// speedup vs baseline: 1.9824x; 1.9824x over previous
#include <cuda_runtime.h>
#include <cuda_bf16.h>
#include <math.h>
#include <stdint.h>

#define Bsz  96
#define Hs   96
#define Ds   768
#define H2   9216
#define KQVN 27648

// ---------------- scratch (static device memory, no allocation) ----------------
__device__ float g_i[Bsz * Hs];
__device__ float g_f[Bsz * Hs];
__device__ float g_o[Bsz * H2];
__device__ float g_kqv[Bsz * KQVN];          // [96, 27648] : k | q | v (k pre-scaled by 1/96)
__device__ float g_vkT_part[16 * Hs * Hs];
__device__ float g_vkT[Hs * Hs];
__device__ int   g_denom[H2];                // float bits (exact, via atomicMax in verify)
__device__ float g_max16[576 * H2];          // per-(16col-group, row) approx |max|, g-major
__device__ int   g_wl[576 * H2];             // worklist (row<<10 | g) — full capacity
__device__ int   g_wlcnt;
// pre-split bf16 operands
__device__ unsigned short g_AT[H2 * 192];    // n^T  [9216, 96hi|96lo]
__device__ unsigned short g_BT[H2 * 192];    // q^T
__device__ unsigned short g_npT[H2 * 192];   // n_prev^T
__device__ unsigned short g_kT[H2 * 192];    // k^T
__device__ unsigned short g_xs[Bsz * 1536];  // x split [96, 768hi|768lo]
__device__ unsigned short g_hps[Bsz * 192];  // h_prev split
__device__ unsigned short g_fis[Bsz * 384];  // [f hi|lo | i hi|lo]
__device__ unsigned short g_Cs[Bsz * 192];   // C split

// ---------------- helpers ----------------
__device__ __forceinline__ uint32_t smem_u32(const void* p) {
    uint32_t a;
    asm("{ .reg .u64 t; cvta.to.shared.u64 t, %1; cvt.u32.u64 %0, t; }" : "=r"(a) : "l"(p));
    return a;
}
#define LDSM_X4(r0, r1, r2, r3, addr) \
    asm volatile("ldmatrix.sync.aligned.m8n8.x4.shared.b16 {%0,%1,%2,%3}, [%4];" \
                 : "=r"(r0), "=r"(r1), "=r"(r2), "=r"(r3) : "r"(addr))
#define MMA16816(d, a, b0, b1) \
    asm volatile("mma.sync.aligned.m16n8k16.row.col.f32.bf16.bf16.f32 " \
                 "{%0,%1,%2,%3},{%4,%5,%6,%7},{%8,%9},{%0,%1,%2,%3};" \
                 : "+f"((d)[0]), "+f"((d)[1]), "+f"((d)[2]), "+f"((d)[3]) \
                 : "r"((a)[0]), "r"((a)[1]), "r"((a)[2]), "r"((a)[3]), "r"(b0), "r"(b1))

// ---------------- misc splits + denom/counter zero, one launch ----------------
__global__ __launch_bounds__(256)
void split_misc(const float* __restrict__ x, const float* __restrict__ hp,
                unsigned short* __restrict__ xs_u16, unsigned short* __restrict__ hps_u16,
                int* __restrict__ denom, int* __restrict__ wlcnt) {
    int blk = blockIdx.x, tid = threadIdx.x;
    if (blk < 288) {                      // x split: 96x768
        __nv_bfloat16* xs = (__nv_bfloat16*)xs_u16;
        int e = blk * 256 + tid;
        int r = e / Ds, c = e % Ds;
        float v = x[e];
        __nv_bfloat16 hi = __float2bfloat16(v);
        xs[(size_t)r * 1536 + c] = hi;
        xs[(size_t)r * 1536 + Ds + c] = __float2bfloat16(v - __bfloat162float(hi));
    } else if (blk < 324) {               // h_prev split: 96x96
        __nv_bfloat16* hs = (__nv_bfloat16*)hps_u16;
        int e = (blk - 288) * 256 + tid;
        int r = e / Hs, c = e % Hs;
        float v = hp[e];
        __nv_bfloat16 hi = __float2bfloat16(v);
        hs[(size_t)r * 192 + c] = hi;
        hs[(size_t)r * 192 + Hs + c] = __float2bfloat16(v - __bfloat162float(hi));
    } else if (blk < 360) {               // zero denom
        int e = (blk - 324) * 256 + tid;
        denom[e] = 0;
    } else {
        if (tid == 0) *wlcnt = 0;
    }
}

// ---------------- fast transpose+split: dst[r][j]=hi(src[j][r]), dst[r][96+j]=lo ----
__global__ __launch_bounds__(256)
void prep_splitT(const float* __restrict__ src, int ld,
                 unsigned short* __restrict__ dst_u16) {
    __nv_bfloat16* dst = (__nv_bfloat16*)dst_u16;
    __shared__ float t[32][68];
    int r0 = blockIdx.x * 64, j0 = blockIdx.y * 32, tid = threadIdx.x;
#pragma unroll
    for (int it = 0; it < 2; it++) {
        int e = tid + it * 256;
        int jj = e >> 4, c4 = (e & 15) * 4;
        float4 v = *(const float4*)(src + (size_t)(j0 + jj) * ld + r0 + c4);
        *(float4*)&t[jj][c4] = v;
    }
    __syncthreads();
#pragma unroll
    for (int it = 0; it < 2; it++) {
        int e = tid + it * 256;
        int rr = e >> 3, q = e & 7;
        int isLo = q >> 2, jb = (q & 3) * 8;
        __nv_bfloat16 vals[8];
#pragma unroll
        for (int w = 0; w < 8; w++) {
            float f = t[jb + w][rr];
            __nv_bfloat16 hi = __float2bfloat16(f);
            vals[w] = isLo ? __float2bfloat16(f - __bfloat162float(hi)) : hi;
        }
        *(uint4*)(dst + (size_t)(r0 + rr) * 192 + isLo * 96 + j0 + jb) = *(uint4*)vals;
    }
}

// ---------------- gates: i = exp(x wix^T + b), f = exp(hp wfx^T + b), + split ----
__global__ __launch_bounds__(256)
void gates_kernel(const float* __restrict__ x, const float* __restrict__ hp,
                  const float* __restrict__ wix_w, const float* __restrict__ wix_b,
                  const float* __restrict__ wfx_w, const float* __restrict__ wfx_b,
                  float* __restrict__ gi, float* __restrict__ gf,
                  unsigned short* __restrict__ fis_u16) {
    int gw = blockIdx.x * 8 + (threadIdx.x >> 5);
    int lane = threadIdx.x & 31;
    int isI = gw < Bsz * Hs;
    int o = isI ? gw : gw - Bsz * Hs;
    int b = o / Hs, n = o % Hs;
    const float* a = isI ? x + (size_t)b * Ds : hp + (size_t)b * Hs;
    const float* w = isI ? wix_w + (size_t)n * Ds : wfx_w + (size_t)n * Hs;
    int K = isI ? Ds : Hs;
    float acc = 0.f;
    for (int k = lane; k < K; k += 32) acc += a[k] * w[k];
#pragma unroll
    for (int off = 16; off; off >>= 1) acc += __shfl_xor_sync(0xffffffffu, acc, off);
    if (lane == 0) {
        float v = expf(acc + (isI ? wix_b[n] : wfx_b[n]));
        (isI ? gi : gf)[o] = v;
        __nv_bfloat16* fis = (__nv_bfloat16*)fis_u16;
        __nv_bfloat16 hi = __float2bfloat16(v);
        int base = b * 384 + (isI ? 192 : 0) + n;
        fis[base] = hi;
        fis[base + 96] = __float2bfloat16(v - __bfloat162float(hi));
    }
}

// ======== Variant A: HMMA NT GEMM (N-tile 64, occ 3), B fp32 converted on the fly ====
// EPI 0: kqv (bias + scale k) + fused kT/qT transpose-split epilogue
// EPI 1: sigmoid(bias)
template <int EPI, int KTOT>
__global__ __launch_bounds__(256, 3)
void hmma_convA(const unsigned short* __restrict__ Asp_u16,
                const float* __restrict__ Bm,
                const float* __restrict__ bias,
                float* __restrict__ out, int ldo,
                unsigned short* __restrict__ kT_u16,
                unsigned short* __restrict__ qT_u16) {
    const __nv_bfloat16* Asp = (const __nv_bfloat16*)Asp_u16;
    extern __shared__ __nv_bfloat16 dyn[];
    __nv_bfloat16* sAr = dyn;                        // [96][72]
    __nv_bfloat16* sBr = dyn + 96 * 72;              // [64][72]
    __nv_bfloat16* sT  = dyn + 96 * 72 + 64 * 72;    // [64][192] (EPI 0 only)
    int tid = threadIdx.x, warp = tid >> 5, lane = tid & 31;
    int n0 = blockIdx.x * 64;
    int wm = warp & 1, wn = warp >> 1;
    float acc[3][2][4] = {};

    uint4 aPre[3];
    float4 bPre[2];
    const int NC = KTOT / 32;

#pragma unroll 1
    for (int c = 0; c < NC; c++) {
        if (c == 0) {
#pragma unroll
            for (int t = 0; t < 3; t++) {
                int e = tid + t * 256;
                int r = e >> 3, col = (e & 7) * 8;
                int sc = (col < 32) ? col : (KTOT + col - 32);
                aPre[t] = *(const uint4*)(Asp + (size_t)r * (2 * KTOT) + sc);
            }
#pragma unroll
            for (int t = 0; t < 2; t++) {
                int e = tid + t * 256;
                int r = e >> 3, g = e & 7;
                bPre[t] = *(const float4*)(Bm + (size_t)(n0 + r) * KTOT + g * 4);
            }
        }
        __syncthreads();
#pragma unroll
        for (int t = 0; t < 3; t++) {
            int e = tid + t * 256;
            int r = e >> 3, col = (e & 7) * 8;
            *(uint4*)&sAr[r * 72 + col] = aPre[t];
        }
#pragma unroll
        for (int t = 0; t < 2; t++) {
            int e = tid + t * 256;
            int r = e >> 3, g = e & 7;
            float vv[4] = {bPre[t].x, bPre[t].y, bPre[t].z, bPre[t].w};
#pragma unroll
            for (int j = 0; j < 4; j++) {
                __nv_bfloat16 hi = __float2bfloat16(vv[j]);
                sBr[r * 72 + g * 4 + j] = hi;
                sBr[r * 72 + 32 + g * 4 + j] = __float2bfloat16(vv[j] - __bfloat162float(hi));
            }
        }
        __syncthreads();
        if (c + 1 < NC) {
            int k0 = (c + 1) * 32;
#pragma unroll
            for (int t = 0; t < 3; t++) {
                int e = tid + t * 256;
                int r = e >> 3, col = (e & 7) * 8;
                int sc = (col < 32) ? (k0 + col) : (KTOT + k0 + col - 32);
                aPre[t] = *(const uint4*)(Asp + (size_t)r * (2 * KTOT) + sc);
            }
#pragma unroll
            for (int t = 0; t < 2; t++) {
                int e = tid + t * 256;
                int r = e >> 3, g = e & 7;
                bPre[t] = *(const float4*)(Bm + (size_t)(n0 + r) * KTOT + k0 + g * 4);
            }
        }
        uint32_t aBase = smem_u32(sAr);
        uint32_t bBase = smem_u32(sBr);
        int aRow = wm * 48 + (lane & 15);
        int aCol = (lane >> 4) << 3;
        int bRow = wn * 16 + (lane & 7) + ((lane >> 4) << 3);
        int bCol = ((lane >> 3) & 1) << 3;
        // merged passes: A_hi x (B_hi, B_lo)
#pragma unroll
        for (int ks = 0; ks < 2; ks++) {
            int ka = ks * 16 + aCol, kb = ks * 16 + bCol;
            uint32_t af[3][4], bh[4], bl[4];
#pragma unroll
            for (int mi = 0; mi < 3; mi++) {
                uint32_t addr = aBase + (uint32_t)(((aRow + mi * 16) * 72 + ka) * 2);
                LDSM_X4(af[mi][0], af[mi][1], af[mi][2], af[mi][3], addr);
            }
            {
                uint32_t addr = bBase + (uint32_t)((bRow * 72 + kb) * 2);
                LDSM_X4(bh[0], bh[1], bh[2], bh[3], addr);
                addr = bBase + (uint32_t)((bRow * 72 + kb + 32) * 2);
                LDSM_X4(bl[0], bl[1], bl[2], bl[3], addr);
            }
#pragma unroll
            for (int mi = 0; mi < 3; mi++)
#pragma unroll
                for (int nj = 0; nj < 2; nj++) {
                    MMA16816(acc[mi][nj], af[mi], bh[nj * 2], bh[nj * 2 + 1]);
                    MMA16816(acc[mi][nj], af[mi], bl[nj * 2], bl[nj * 2 + 1]);
                }
        }
        // pass 2: A_lo x B_hi
#pragma unroll
        for (int ks = 0; ks < 2; ks++) {
            int ka = 32 + ks * 16 + aCol, kb = ks * 16 + bCol;
            uint32_t af[3][4], bh[4];
#pragma unroll
            for (int mi = 0; mi < 3; mi++) {
                uint32_t addr = aBase + (uint32_t)(((aRow + mi * 16) * 72 + ka) * 2);
                LDSM_X4(af[mi][0], af[mi][1], af[mi][2], af[mi][3], addr);
            }
            {
                uint32_t addr = bBase + (uint32_t)((bRow * 72 + kb) * 2);
                LDSM_X4(bh[0], bh[1], bh[2], bh[3], addr);
            }
#pragma unroll
            for (int mi = 0; mi < 3; mi++)
#pragma unroll
                for (int nj = 0; nj < 2; nj++)
                    MMA16816(acc[mi][nj], af[mi], bh[nj * 2], bh[nj * 2 + 1]);
        }
    }
    const bool doT = (EPI == 0) && (n0 < 2 * H2);
#pragma unroll
    for (int mi = 0; mi < 3; mi++)
#pragma unroll
        for (int nj = 0; nj < 2; nj++)
#pragma unroll
            for (int r = 0; r < 4; r++) {
                int m = wm * 48 + mi * 16 + (lane >> 2) + ((r >> 1) * 8);
                int gl = wn * 16 + nj * 8 + (lane & 3) * 2 + (r & 1);
                int gn = n0 + gl;
                float v = acc[mi][nj][r] + bias[gn];
                if (EPI == 0) { if (gn < H2) v *= (1.0f / 96.0f); }
                if (EPI == 1) v = 1.0f / (1.0f + expf(-v));
                out[(size_t)m * ldo + gn] = v;
                if (doT) {
                    __nv_bfloat16 hi = __float2bfloat16(v);
                    sT[gl * 192 + m] = hi;
                    sT[gl * 192 + 96 + m] = __float2bfloat16(v - __bfloat162float(hi));
                }
            }
    if (doT) {
        __syncthreads();
        __nv_bfloat16* dstT = (__nv_bfloat16*)((n0 < H2) ? kT_u16 : qT_u16);
        int cb = (n0 < H2) ? n0 : (n0 - H2);
        for (int e = tid; e < 64 * 24; e += 256) {
            int row = e / 24, g = e % 24;
            *(uint4*)(dstT + (size_t)(cb + row) * 192 + g * 8) = *(uint4*)(sT + row * 192 + g * 8);
        }
    }
}

// ======== Variant B: HMMA NT GEMM, pre-split bf16 B [N, 192], up to 2 K-segments ====
// EPI 2: n (+ fused AT transpose-split), EPI 3: h = o * acc / denom
template <int EPI>
__global__ __launch_bounds__(256, 2)
void hmma_preB(const unsigned short* __restrict__ Asp_u16, int lda,
               const unsigned short* __restrict__ B1_u16,
               const unsigned short* __restrict__ B2_u16,
               int nseg,
               const float* __restrict__ omat,
               const int* __restrict__ denomBits,
               float* __restrict__ out, int ldo,
               unsigned short* __restrict__ AT_u16) {
    const __nv_bfloat16* Asp = (const __nv_bfloat16*)Asp_u16;
    extern __shared__ __nv_bfloat16 dsm[];
    __nv_bfloat16* sA = dsm;             // [96][200]
    __nv_bfloat16* sB = dsm + 96 * 200;  // [64][200]
    int tid = threadIdx.x, warp = tid >> 5, lane = tid & 31;
    int n0 = blockIdx.x * 64;
    int wm = warp & 1, wn = warp >> 1;
    float acc[3][2][4] = {};

#pragma unroll 1
    for (int s = 0; s < nseg; s++) {
        const __nv_bfloat16* Bseg =
            (s == 0) ? (const __nv_bfloat16*)B1_u16 : (const __nv_bfloat16*)B2_u16;
        __syncthreads();
        for (int e = tid; e < 96 * 24; e += 256) {
            int r = e / 24, g = e % 24;
            *(uint4*)(sA + r * 200 + g * 8) =
                *(const uint4*)(Asp + (size_t)r * lda + s * 192 + g * 8);
        }
        for (int e = tid; e < 64 * 24; e += 256) {
            int r = e / 24, g = e % 24;
            *(uint4*)(sB + r * 200 + g * 8) =
                *(const uint4*)(Bseg + (size_t)(n0 + r) * 192 + g * 8);
        }
        __syncthreads();
        uint32_t aBase = smem_u32(sA), bBase = smem_u32(sB);
        int aRow = wm * 48 + (lane & 15), aCol = (lane >> 4) << 3;
        int bRow = wn * 16 + (lane & 7) + ((lane >> 4) << 3);
        int bCol = ((lane >> 3) & 1) << 3;
        // merged passes: A_hi x (B_hi, B_lo)
#pragma unroll
        for (int ks = 0; ks < 6; ks++) {
            int ka = ks * 16 + aCol, kb = ks * 16 + bCol;
            uint32_t af[3][4], bh[4], bl[4];
#pragma unroll
            for (int mi = 0; mi < 3; mi++) {
                uint32_t addr = aBase + (uint32_t)(((aRow + mi * 16) * 200 + ka) * 2);
                LDSM_X4(af[mi][0], af[mi][1], af[mi][2], af[mi][3], addr);
            }
            {
                uint32_t addr = bBase + (uint32_t)((bRow * 200 + kb) * 2);
                LDSM_X4(bh[0], bh[1], bh[2], bh[3], addr);
                addr = bBase + (uint32_t)((bRow * 200 + kb + 96) * 2);
                LDSM_X4(bl[0], bl[1], bl[2], bl[3], addr);
            }
#pragma unroll
            for (int mi = 0; mi < 3; mi++)
#pragma unroll
                for (int nj = 0; nj < 2; nj++) {
                    MMA16816(acc[mi][nj], af[mi], bh[nj * 2], bh[nj * 2 + 1]);
                    MMA16816(acc[mi][nj], af[mi], bl[nj * 2], bl[nj * 2 + 1]);
                }
        }
        // pass 2: A_lo x B_hi
#pragma unroll
        for (int ks = 0; ks < 6; ks++) {
            int ka = 96 + ks * 16 + aCol, kb = ks * 16 + bCol;
            uint32_t af[3][4], bh[4];
#pragma unroll
            for (int mi = 0; mi < 3; mi++) {
                uint32_t addr = aBase + (uint32_t)(((aRow + mi * 16) * 200 + ka) * 2);
                LDSM_X4(af[mi][0], af[mi][1], af[mi][2], af[mi][3], addr);
            }
            {
                uint32_t addr = bBase + (uint32_t)((bRow * 200 + kb) * 2);
                LDSM_X4(bh[0], bh[1], bh[2], bh[3], addr);
            }
#pragma unroll
            for (int mi = 0; mi < 3; mi++)
#pragma unroll
                for (int nj = 0; nj < 2; nj++)
                    MMA16816(acc[mi][nj], af[mi], bh[nj * 2], bh[nj * 2 + 1]);
        }
    }
    if (EPI == 2) __syncthreads();   // before reusing sA as staging
#pragma unroll
    for (int mi = 0; mi < 3; mi++)
#pragma unroll
        for (int nj = 0; nj < 2; nj++)
#pragma unroll
            for (int r = 0; r < 4; r++) {
                int m = wm * 48 + mi * 16 + (lane >> 2) + ((r >> 1) * 8);
                int gl = wn * 16 + nj * 8 + (lane & 3) * 2 + (r & 1);
                int gn = n0 + gl;
                float v = acc[mi][nj][r];
                if (EPI == 3)
                    v = omat[(size_t)m * H2 + gn] * v / __int_as_float(denomBits[gn]);
                out[(size_t)m * ldo + gn] = v;
                if (EPI == 2) {
                    __nv_bfloat16 hi = __float2bfloat16(v);
                    sA[gl * 192 + m] = hi;
                    sA[gl * 192 + 96 + m] = __float2bfloat16(v - __bfloat162float(hi));
                }
            }
    if (EPI == 2) {
        __syncthreads();
        __nv_bfloat16* AT = (__nv_bfloat16*)AT_u16;
        for (int e = tid; e < 64 * 24; e += 256) {
            int row = e / 24, g = e % 24;
            *(uint4*)(AT + (size_t)(n0 + row) * 192 + g * 8) = *(uint4*)(sA + row * 192 + g * 8);
        }
    }
}

// ================= denom phase 1: single hi-pass screen =================
#define SMP 104

__global__ __launch_bounds__(256, 2)
void denom_p1_kernel(const unsigned short* __restrict__ AT,
                     const unsigned short* __restrict__ BT,
                     float* __restrict__ gmax16) {
    extern __shared__ __align__(16) unsigned short sm[];
    unsigned short* sA = sm;
    unsigned short* sB = sm + 128 * SMP;
    int tid = threadIdx.x;
    int r0 = blockIdx.x * 128, c0 = blockIdx.y * 128;

    for (int e = tid; e < 128 * 12; e += 256) {
        int row = e / 12, c8 = (e % 12) * 8;
        *(float4*)(sA + row * SMP + c8) = *(const float4*)(AT + (size_t)(r0 + row) * 192 + c8);
        *(float4*)(sB + row * SMP + c8) = *(const float4*)(BT + (size_t)(c0 + row) * 192 + c8);
    }
    __syncthreads();

    int warp = tid >> 5, lane = tid & 31;
    int wm = warp & 1, wn = warp >> 1;
    uint32_t aBase = smem_u32(sA);
    uint32_t bBase = smem_u32(sB);

    float acc[4][4][4];
#pragma unroll
    for (int mi = 0; mi < 4; mi++)
#pragma unroll
        for (int nj = 0; nj < 4; nj++)
#pragma unroll
            for (int r = 0; r < 4; r++) acc[mi][nj][r] = 0.f;

    int aRow = wm * 64 + (lane & 15);
    int aColL = (lane >> 4) << 3;
    int bRow = wn * 32 + (lane & 7) + ((lane >> 4) << 3);
    int bColL = ((lane >> 3) & 1) << 3;

#pragma unroll 1
    for (int ks = 0; ks < 6; ks++) {
        int ka = ks * 16 + aColL;
        int kb = ks * 16 + bColL;
        uint32_t af[4][4], bh[2][4];
#pragma unroll
        for (int mi = 0; mi < 4; mi++) {
            uint32_t addr = aBase + (uint32_t)(((aRow + mi * 16) * SMP + ka) * 2);
            LDSM_X4(af[mi][0], af[mi][1], af[mi][2], af[mi][3], addr);
        }
#pragma unroll
        for (int nj2 = 0; nj2 < 2; nj2++) {
            uint32_t addr = bBase + (uint32_t)(((bRow + nj2 * 16) * SMP + kb) * 2);
            LDSM_X4(bh[nj2][0], bh[nj2][1], bh[nj2][2], bh[nj2][3], addr);
        }
#pragma unroll
        for (int mi = 0; mi < 4; mi++)
#pragma unroll
            for (int nj = 0; nj < 4; nj++)
                MMA16816(acc[mi][nj], af[mi], bh[nj >> 1][(nj & 1) * 2],
                         bh[nj >> 1][(nj & 1) * 2 + 1]);
    }

#pragma unroll
    for (int mi = 0; mi < 4; mi++) {
        float g0a = fmaxf(fmaxf(fabsf(acc[mi][0][0]), fabsf(acc[mi][0][1])),
                          fmaxf(fabsf(acc[mi][1][0]), fabsf(acc[mi][1][1])));
        float g0b = fmaxf(fmaxf(fabsf(acc[mi][0][2]), fabsf(acc[mi][0][3])),
                          fmaxf(fabsf(acc[mi][1][2]), fabsf(acc[mi][1][3])));
        float g1a = fmaxf(fmaxf(fabsf(acc[mi][2][0]), fabsf(acc[mi][2][1])),
                          fmaxf(fabsf(acc[mi][3][0]), fabsf(acc[mi][3][1])));
        float g1b = fmaxf(fmaxf(fabsf(acc[mi][2][2]), fabsf(acc[mi][2][3])),
                          fmaxf(fabsf(acc[mi][3][2]), fabsf(acc[mi][3][3])));
#pragma unroll
        for (int off = 1; off <= 2; off <<= 1) {
            g0a = fmaxf(g0a, __shfl_xor_sync(0xffffffffu, g0a, off));
            g0b = fmaxf(g0b, __shfl_xor_sync(0xffffffffu, g0b, off));
            g1a = fmaxf(g1a, __shfl_xor_sync(0xffffffffu, g1a, off));
            g1b = fmaxf(g1b, __shfl_xor_sync(0xffffffffu, g1b, off));
        }
        if ((lane & 3) == 0) {
            int rr = r0 + wm * 64 + mi * 16 + (lane >> 2);
            size_t gb = (size_t)(blockIdx.y * 8 + wn * 2);
            gmax16[gb * H2 + rr]           = g0a;
            gmax16[gb * H2 + rr + 8]       = g0b;
            gmax16[(gb + 1) * H2 + rr]     = g1a;
            gmax16[(gb + 1) * H2 + rr + 8] = g1b;
        }
    }
}

// ================= denom flag: build (row,group) worklist =================
__global__ __launch_bounds__(256)
void denom_flag(const float* __restrict__ gmax16,
                int* __restrict__ wl, int* __restrict__ wlcnt) {
    int r = blockIdx.x * 256 + threadIdx.x;   // row, coalesced across threads
    float rmax = 0.f;
    for (int g = 0; g < 576; g++)
        rmax = fmaxf(rmax, gmax16[(size_t)g * H2 + r]);
    float thresh = 0.93f * rmax;
    for (int g = 0; g < 576; g++) {
        if (gmax16[(size_t)g * H2 + r] >= thresh) {
            int idx = atomicAdd(wlcnt, 1);
            wl[idx] = (r << 10) | g;
        }
    }
}

// ================= denom verify: one warp per flagged (row,group), exact fp32 ====
__global__ __launch_bounds__(256)
void denom_verify(const int* __restrict__ wl, const int* __restrict__ wlcnt,
                  const float* __restrict__ nmat,   // out_n [96, 9216]
                  const float* __restrict__ kqv,    // q at + H2, ld = KQVN
                  int* __restrict__ denomBits) {
    int cnt = *wlcnt;
    int gwarp = (blockIdx.x * 256 + threadIdx.x) >> 5;
    int nwarps = (gridDim.x * 256) >> 5;
    int lane = threadIdx.x & 31;
    const float* q = kqv + H2;
    for (int e = gwarp; e < cnt; e += nwarps) {
        int ent = wl[e];
        int row = ent >> 10, g = ent & 1023;
        int c = g * 16 + (lane & 15);
        int b0 = (lane >> 4) * 48;
        float acc = 0.f;
#pragma unroll 8
        for (int b = 0; b < 48; b++)
            acc += __ldg(&nmat[(size_t)(b0 + b) * H2 + row]) *
                   __ldg(&q[(size_t)(b0 + b) * KQVN + c]);
        acc += __shfl_xor_sync(0xffffffffu, acc, 16);
        float a = fabsf(acc);
#pragma unroll
        for (int off = 8; off; off >>= 1)
            a = fmaxf(a, __shfl_xor_sync(0xffffffffu, a, off));
        if (lane == 0) atomicMax(&denomBits[row], __float_as_int(a));
    }
}

// ---------------- v @ k^T : deterministic split-K (16 chunks of 576) ----------------
__global__ __launch_bounds__(256)
void vkt_part_kernel(const float* __restrict__ kqv, float* __restrict__ part) {
    const float* V  = kqv + 2 * H2;
    const float* Km = kqv;
    __shared__ float As[32][17];
    __shared__ float Bs[32][17];
    int tid = threadIdx.x, tx = tid & 15, ty = tid >> 4;
    int m0 = blockIdx.x * 32, n0 = blockIdx.y * 32;
    int kbase = blockIdx.z * 576;
    float a00 = 0, a01 = 0, a10 = 0, a11 = 0;
    for (int k0 = 0; k0 < 576; k0 += 16) {
        for (int e = tid; e < 32 * 16; e += 256) {
            int m = e >> 4, k = e & 15;
            As[m][k] = V[(size_t)(m0 + m) * KQVN + kbase + k0 + k];
            Bs[m][k] = Km[(size_t)(n0 + m) * KQVN + kbase + k0 + k];
        }
        __syncthreads();
#pragma unroll
        for (int kk = 0; kk < 16; kk++) {
            float av0 = As[ty][kk],      av1 = As[ty + 16][kk];
            float bv0 = Bs[tx][kk],      bv1 = Bs[tx + 16][kk];
            a00 += av0 * bv0; a01 += av0 * bv1;
            a10 += av1 * bv0; a11 += av1 * bv1;
        }
        __syncthreads();
    }
    float* p = part + blockIdx.z * (Hs * Hs);
    p[(m0 + ty) * Hs + (n0 + tx)]           = a00;
    p[(m0 + ty) * Hs + (n0 + tx + 16)]      = a01;
    p[(m0 + ty + 16) * Hs + (n0 + tx)]      = a10;
    p[(m0 + ty + 16) * Hs + (n0 + tx + 16)] = a11;
}

__global__ void vkt_reduce_kernel(const float* __restrict__ part, float* __restrict__ vkt) {
    int idx = blockIdx.x * blockDim.x + threadIdx.x;
    if (idx < Hs * Hs) {
        float s = 0.f;
#pragma unroll
        for (int c = 0; c < 16; c++) s += part[c * (Hs * Hs) + idx];
        vkt[idx] = s;
    }
}

// ---------------- C = f @ C_prev + i @ vkT   (96x96), + split ----------------
__global__ void c_kernel(const float* __restrict__ f, const float* __restrict__ i_,
                         const float* __restrict__ C_prev, const float* __restrict__ vkt,
                         float* __restrict__ outC, unsigned short* __restrict__ Cs_u16) {
    __shared__ float fs[Hs], is[Hs];
    int b = blockIdx.x, n = threadIdx.x;
    fs[n] = f[b * Hs + n];
    is[n] = i_[b * Hs + n];
    __syncthreads();
    float acc = 0.f;
    for (int h = 0; h < Hs; h++)
        acc += fs[h] * C_prev[h * Hs + n] + is[h] * vkt[h * Hs + n];
    outC[b * Hs + n] = acc;
    __nv_bfloat16* Cs = (__nv_bfloat16*)Cs_u16;
    __nv_bfloat16 hi = __float2bfloat16(acc);
    Cs[b * 192 + n] = hi;
    Cs[b * 192 + 96 + n] = __float2bfloat16(acc - __bfloat162float(hi));
}

// ---------------- launch ----------------
extern "C" void kernel_launch(void* const* d_in, const int* in_sizes, int n_in,
                              void* d_out, int out_size) {
    const float* x      = (const float*)d_in[0];
    const float* h_prev = (const float*)d_in[1];
    const float* C_prev = (const float*)d_in[2];
    const float* n_prev = (const float*)d_in[3];
    const float* wix_w  = (const float*)d_in[4];
    const float* wix_b  = (const float*)d_in[5];
    const float* wfx_w  = (const float*)d_in[6];
    const float* wfx_b  = (const float*)d_in[7];
    const float* Wox_w  = (const float*)d_in[8];
    const float* Wox_b  = (const float*)d_in[9];
    const float* Wkqv_w = (const float*)d_in[10];
    const float* Wkqv_b = (const float*)d_in[11];

    float* out   = (float*)d_out;
    float* out_h = out;                       // [96, 9216]
    float* out_C = out + Bsz * H2;            // [96, 96]
    float* out_n = out_C + Bsz * Hs;          // [96, 9216]

    float *p_i, *p_f, *p_o, *p_kqv, *p_part, *p_vkt, *p_gmax;
    int *p_denom, *p_wl, *p_wlcnt;
    unsigned short *p_AT, *p_BT, *p_npT, *p_kT, *p_xs, *p_hps, *p_fis, *p_Cs;
    cudaGetSymbolAddress((void**)&p_i,     g_i);
    cudaGetSymbolAddress((void**)&p_f,     g_f);
    cudaGetSymbolAddress((void**)&p_o,     g_o);
    cudaGetSymbolAddress((void**)&p_kqv,   g_kqv);
    cudaGetSymbolAddress((void**)&p_part,  g_vkT_part);
    cudaGetSymbolAddress((void**)&p_vkt,   g_vkT);
    cudaGetSymbolAddress((void**)&p_denom, g_denom);
    cudaGetSymbolAddress((void**)&p_gmax,  g_max16);
    cudaGetSymbolAddress((void**)&p_wl,    g_wl);
    cudaGetSymbolAddress((void**)&p_wlcnt, g_wlcnt);
    cudaGetSymbolAddress((void**)&p_AT,    g_AT);
    cudaGetSymbolAddress((void**)&p_BT,    g_BT);
    cudaGetSymbolAddress((void**)&p_npT,   g_npT);
    cudaGetSymbolAddress((void**)&p_kT,    g_kT);
    cudaGetSymbolAddress((void**)&p_xs,    g_xs);
    cudaGetSymbolAddress((void**)&p_hps,   g_hps);
    cudaGetSymbolAddress((void**)&p_fis,   g_fis);
    cudaGetSymbolAddress((void**)&p_Cs,    g_Cs);

    const int P1_SMEM    = 2 * 128 * SMP * 2;                    // 53248
    const int PREB_SMEM  = (96 + 64) * 200 * 2;                  // 64000
    const int CONV_SMEM  = (96 * 72 + 64 * 72 + 64 * 192) * 2;   // 47616
    const int CONV1_SMEM = (96 * 72 + 64 * 72) * 2;              // 23040
    cudaFuncSetAttribute(denom_p1_kernel,
                         cudaFuncAttributeMaxDynamicSharedMemorySize, P1_SMEM);
    cudaFuncSetAttribute(hmma_preB<2>,
                         cudaFuncAttributeMaxDynamicSharedMemorySize, PREB_SMEM);
    cudaFuncSetAttribute(hmma_preB<3>,
                         cudaFuncAttributeMaxDynamicSharedMemorySize, PREB_SMEM);
    cudaFuncSetAttribute(hmma_convA<0, Ds>,
                         cudaFuncAttributeMaxDynamicSharedMemorySize, CONV_SMEM);
    cudaFuncSetAttribute(hmma_convA<1, Hs>,
                         cudaFuncAttributeMaxDynamicSharedMemorySize, CONV1_SMEM);

    // x/h_prev splits + denom/counter zero (one launch)
    split_misc<<<361, 256>>>(x, h_prev, p_xs, p_hps, p_denom, p_wlcnt);

    // n_prev^T split
    prep_splitT<<<dim3(H2 / 64, 3), 256>>>(n_prev, H2, p_npT);

    // i, f gates + split
    gates_kernel<<<2304, 256>>>(x, h_prev, wix_w, wix_b, wfx_w, wfx_b, p_i, p_f, p_fis);

    // kqv = x @ Wkqv^T + b (HMMA) + fused kT/qT transpose-splits
    hmma_convA<0, Ds><<<KQVN / 64, 256, CONV_SMEM>>>(p_xs, Wkqv_w, Wkqv_b, p_kqv, KQVN,
                                                     p_kT, p_BT);

    // o = sigmoid(h_prev @ Wox^T + b)
    hmma_convA<1, Hs><<<H2 / 64, 256, CONV1_SMEM>>>(p_hps, Wox_w, Wox_b, p_o, H2,
                                                    nullptr, nullptr);

    // n = f @ n_prev + i @ k  (HMMA) + fused AT transpose-split
    hmma_preB<2><<<H2 / 64, 256, PREB_SMEM>>>(p_fis, 384, p_npT, p_kT, 2,
                                              nullptr, nullptr, out_n, H2, p_AT);

    // vkT = v @ k^T
    vkt_part_kernel<<<dim3(3, 3, 16), 256>>>(p_kqv, p_part);
    vkt_reduce_kernel<<<36, 256>>>(p_part, p_vkt);

    // C = f @ C_prev + i @ vkT (+ split)
    c_kernel<<<Bsz, Hs>>>(p_f, p_i, C_prev, p_vkt, out_C, p_Cs);

    // denom: screen -> flag -> parallel exact verify
    denom_p1_kernel<<<dim3(72, 72), 256, P1_SMEM>>>(p_AT, p_BT, p_gmax);
    denom_flag<<<36, 256>>>(p_gmax, p_wl, p_wlcnt);
    denom_verify<<<1184, 256>>>(p_wl, p_wlcnt, out_n, p_kqv, p_denom);

    // h = o * (C @ q) / denom
    hmma_preB<3><<<H2 / 64, 256, PREB_SMEM>>>(p_Cs, 192, p_BT, nullptr, 1,
                                              p_o, p_denom, out_h, H2, nullptr);
}

// round 10
// speedup vs baseline: 2.3735x; 1.1973x over previous
#include <cuda_runtime.h>
#include <cuda_bf16.h>
#include <math.h>
#include <stdint.h>

#define Bsz  96
#define Hs   96
#define Ds   768
#define H2   9216
#define KQVN 27648

// ---------------- scratch (static device memory, no allocation) ----------------
__device__ float g_i[Bsz * Hs];
__device__ float g_f[Bsz * Hs];
__device__ float g_o[Bsz * H2];
__device__ float g_kqv[Bsz * KQVN];          // [96, 27648] : k | q | v (k pre-scaled by 1/96)
__device__ float g_vkT_part[16 * Hs * Hs];
__device__ float g_vkT[Hs * Hs];
__device__ int   g_denom[H2];                // float bits via atomicMax on non-neg floats
// pre-split bf16 operands
__device__ unsigned short g_AT[H2 * 192];    // n^T  [9216, 96hi|96lo]
__device__ unsigned short g_BT[H2 * 192];    // q^T
__device__ unsigned short g_npT[H2 * 192];   // n_prev^T
__device__ unsigned short g_kT[H2 * 192];    // k^T
__device__ unsigned short g_xs[Bsz * 1536];  // x split [96, 768hi|768lo]
__device__ unsigned short g_hps[Bsz * 192];  // h_prev split
__device__ unsigned short g_fis[Bsz * 384];  // [f hi|lo | i hi|lo]
__device__ unsigned short g_Cs[Bsz * 192];   // C split

// ---------------- helpers ----------------
__device__ __forceinline__ uint32_t smem_u32(const void* p) {
    uint32_t a;
    asm("{ .reg .u64 t; cvta.to.shared.u64 t, %1; cvt.u32.u64 %0, t; }" : "=r"(a) : "l"(p));
    return a;
}
#define LDSM_X4(r0, r1, r2, r3, addr) \
    asm volatile("ldmatrix.sync.aligned.m8n8.x4.shared.b16 {%0,%1,%2,%3}, [%4];" \
                 : "=r"(r0), "=r"(r1), "=r"(r2), "=r"(r3) : "r"(addr))
#define MMA16816(d, a, b0, b1) \
    asm volatile("mma.sync.aligned.m16n8k16.row.col.f32.bf16.bf16.f32 " \
                 "{%0,%1,%2,%3},{%4,%5,%6,%7},{%8,%9},{%0,%1,%2,%3};" \
                 : "+f"((d)[0]), "+f"((d)[1]), "+f"((d)[2]), "+f"((d)[3]) \
                 : "r"((a)[0]), "r"((a)[1]), "r"((a)[2]), "r"((a)[3]), "r"(b0), "r"(b1))

// ---------------- misc splits + denom zero, one launch ----------------
__global__ __launch_bounds__(256)
void split_misc(const float* __restrict__ x, const float* __restrict__ hp,
                unsigned short* __restrict__ xs_u16, unsigned short* __restrict__ hps_u16,
                int* __restrict__ denom) {
    int blk = blockIdx.x, tid = threadIdx.x;
    if (blk < 288) {                      // x split: 96x768
        __nv_bfloat16* xs = (__nv_bfloat16*)xs_u16;
        int e = blk * 256 + tid;
        int r = e / Ds, c = e % Ds;
        float v = x[e];
        __nv_bfloat16 hi = __float2bfloat16(v);
        xs[(size_t)r * 1536 + c] = hi;
        xs[(size_t)r * 1536 + Ds + c] = __float2bfloat16(v - __bfloat162float(hi));
    } else if (blk < 324) {               // h_prev split: 96x96
        __nv_bfloat16* hs = (__nv_bfloat16*)hps_u16;
        int e = (blk - 288) * 256 + tid;
        int r = e / Hs, c = e % Hs;
        float v = hp[e];
        __nv_bfloat16 hi = __float2bfloat16(v);
        hs[(size_t)r * 192 + c] = hi;
        hs[(size_t)r * 192 + Hs + c] = __float2bfloat16(v - __bfloat162float(hi));
    } else {                              // zero denom
        int e = (blk - 324) * 256 + tid;
        denom[e] = 0;
    }
}

// ---------------- fast transpose+split: dst[r][j]=hi(src[j][r]), dst[r][96+j]=lo ----
__global__ __launch_bounds__(256)
void prep_splitT(const float* __restrict__ src, int ld,
                 unsigned short* __restrict__ dst_u16) {
    __nv_bfloat16* dst = (__nv_bfloat16*)dst_u16;
    __shared__ float t[32][68];
    int r0 = blockIdx.x * 64, j0 = blockIdx.y * 32, tid = threadIdx.x;
#pragma unroll
    for (int it = 0; it < 2; it++) {
        int e = tid + it * 256;
        int jj = e >> 4, c4 = (e & 15) * 4;
        float4 v = *(const float4*)(src + (size_t)(j0 + jj) * ld + r0 + c4);
        *(float4*)&t[jj][c4] = v;
    }
    __syncthreads();
#pragma unroll
    for (int it = 0; it < 2; it++) {
        int e = tid + it * 256;
        int rr = e >> 3, q = e & 7;
        int isLo = q >> 2, jb = (q & 3) * 8;
        __nv_bfloat16 vals[8];
#pragma unroll
        for (int w = 0; w < 8; w++) {
            float f = t[jb + w][rr];
            __nv_bfloat16 hi = __float2bfloat16(f);
            vals[w] = isLo ? __float2bfloat16(f - __bfloat162float(hi)) : hi;
        }
        *(uint4*)(dst + (size_t)(r0 + rr) * 192 + isLo * 96 + j0 + jb) = *(uint4*)vals;
    }
}

// ---------------- gates: i = exp(x wix^T + b), f = exp(hp wfx^T + b), + split ----
__global__ __launch_bounds__(256)
void gates_kernel(const float* __restrict__ x, const float* __restrict__ hp,
                  const float* __restrict__ wix_w, const float* __restrict__ wix_b,
                  const float* __restrict__ wfx_w, const float* __restrict__ wfx_b,
                  float* __restrict__ gi, float* __restrict__ gf,
                  unsigned short* __restrict__ fis_u16) {
    int gw = blockIdx.x * 8 + (threadIdx.x >> 5);
    int lane = threadIdx.x & 31;
    int isI = gw < Bsz * Hs;
    int o = isI ? gw : gw - Bsz * Hs;
    int b = o / Hs, n = o % Hs;
    const float* a = isI ? x + (size_t)b * Ds : hp + (size_t)b * Hs;
    const float* w = isI ? wix_w + (size_t)n * Ds : wfx_w + (size_t)n * Hs;
    int K = isI ? Ds : Hs;
    float acc = 0.f;
    for (int k = lane; k < K; k += 32) acc += a[k] * w[k];
#pragma unroll
    for (int off = 16; off; off >>= 1) acc += __shfl_xor_sync(0xffffffffu, acc, off);
    if (lane == 0) {
        float v = expf(acc + (isI ? wix_b[n] : wfx_b[n]));
        (isI ? gi : gf)[o] = v;
        __nv_bfloat16* fis = (__nv_bfloat16*)fis_u16;
        __nv_bfloat16 hi = __float2bfloat16(v);
        int base = b * 384 + (isI ? 192 : 0) + n;
        fis[base] = hi;
        fis[base + 96] = __float2bfloat16(v - __bfloat162float(hi));
    }
}

// ======== Variant A: HMMA NT GEMM (N-tile 64, occ 3), B fp32 converted on the fly ====
// EPI 0: kqv (bias + scale k) + fused kT/qT transpose-split epilogue
// EPI 1: sigmoid(bias)
template <int EPI, int KTOT>
__global__ __launch_bounds__(256, 3)
void hmma_convA(const unsigned short* __restrict__ Asp_u16,
                const float* __restrict__ Bm,
                const float* __restrict__ bias,
                float* __restrict__ out, int ldo,
                unsigned short* __restrict__ kT_u16,
                unsigned short* __restrict__ qT_u16) {
    const __nv_bfloat16* Asp = (const __nv_bfloat16*)Asp_u16;
    extern __shared__ __nv_bfloat16 dyn[];
    __nv_bfloat16* sAr = dyn;                        // [96][72]
    __nv_bfloat16* sBr = dyn + 96 * 72;              // [64][72]
    __nv_bfloat16* sT  = dyn + 96 * 72 + 64 * 72;    // [64][192] (EPI 0 only)
    int tid = threadIdx.x, warp = tid >> 5, lane = tid & 31;
    int n0 = blockIdx.x * 64;
    int wm = warp & 1, wn = warp >> 1;
    float acc[3][2][4] = {};

    uint4 aPre[3];
    float4 bPre[2];
    const int NC = KTOT / 32;

#pragma unroll 1
    for (int c = 0; c < NC; c++) {
        if (c == 0) {
#pragma unroll
            for (int t = 0; t < 3; t++) {
                int e = tid + t * 256;
                int r = e >> 3, col = (e & 7) * 8;
                int sc = (col < 32) ? col : (KTOT + col - 32);
                aPre[t] = *(const uint4*)(Asp + (size_t)r * (2 * KTOT) + sc);
            }
#pragma unroll
            for (int t = 0; t < 2; t++) {
                int e = tid + t * 256;
                int r = e >> 3, g = e & 7;
                bPre[t] = *(const float4*)(Bm + (size_t)(n0 + r) * KTOT + g * 4);
            }
        }
        __syncthreads();
#pragma unroll
        for (int t = 0; t < 3; t++) {
            int e = tid + t * 256;
            int r = e >> 3, col = (e & 7) * 8;
            *(uint4*)&sAr[r * 72 + col] = aPre[t];
        }
#pragma unroll
        for (int t = 0; t < 2; t++) {
            int e = tid + t * 256;
            int r = e >> 3, g = e & 7;
            float vv[4] = {bPre[t].x, bPre[t].y, bPre[t].z, bPre[t].w};
#pragma unroll
            for (int j = 0; j < 4; j++) {
                __nv_bfloat16 hi = __float2bfloat16(vv[j]);
                sBr[r * 72 + g * 4 + j] = hi;
                sBr[r * 72 + 32 + g * 4 + j] = __float2bfloat16(vv[j] - __bfloat162float(hi));
            }
        }
        __syncthreads();
        if (c + 1 < NC) {
            int k0 = (c + 1) * 32;
#pragma unroll
            for (int t = 0; t < 3; t++) {
                int e = tid + t * 256;
                int r = e >> 3, col = (e & 7) * 8;
                int sc = (col < 32) ? (k0 + col) : (KTOT + k0 + col - 32);
                aPre[t] = *(const uint4*)(Asp + (size_t)r * (2 * KTOT) + sc);
            }
#pragma unroll
            for (int t = 0; t < 2; t++) {
                int e = tid + t * 256;
                int r = e >> 3, g = e & 7;
                bPre[t] = *(const float4*)(Bm + (size_t)(n0 + r) * KTOT + k0 + g * 4);
            }
        }
        uint32_t aBase = smem_u32(sAr);
        uint32_t bBase = smem_u32(sBr);
        int aRow = wm * 48 + (lane & 15);
        int aCol = (lane >> 4) << 3;
        int bRow = wn * 16 + (lane & 7) + ((lane >> 4) << 3);
        int bCol = ((lane >> 3) & 1) << 3;
        // merged passes: A_hi x (B_hi, B_lo)
#pragma unroll
        for (int ks = 0; ks < 2; ks++) {
            int ka = ks * 16 + aCol, kb = ks * 16 + bCol;
            uint32_t af[3][4], bh[4], bl[4];
#pragma unroll
            for (int mi = 0; mi < 3; mi++) {
                uint32_t addr = aBase + (uint32_t)(((aRow + mi * 16) * 72 + ka) * 2);
                LDSM_X4(af[mi][0], af[mi][1], af[mi][2], af[mi][3], addr);
            }
            {
                uint32_t addr = bBase + (uint32_t)((bRow * 72 + kb) * 2);
                LDSM_X4(bh[0], bh[1], bh[2], bh[3], addr);
                addr = bBase + (uint32_t)((bRow * 72 + kb + 32) * 2);
                LDSM_X4(bl[0], bl[1], bl[2], bl[3], addr);
            }
#pragma unroll
            for (int mi = 0; mi < 3; mi++)
#pragma unroll
                for (int nj = 0; nj < 2; nj++) {
                    MMA16816(acc[mi][nj], af[mi], bh[nj * 2], bh[nj * 2 + 1]);
                    MMA16816(acc[mi][nj], af[mi], bl[nj * 2], bl[nj * 2 + 1]);
                }
        }
        // pass 2: A_lo x B_hi
#pragma unroll
        for (int ks = 0; ks < 2; ks++) {
            int ka = 32 + ks * 16 + aCol, kb = ks * 16 + bCol;
            uint32_t af[3][4], bh[4];
#pragma unroll
            for (int mi = 0; mi < 3; mi++) {
                uint32_t addr = aBase + (uint32_t)(((aRow + mi * 16) * 72 + ka) * 2);
                LDSM_X4(af[mi][0], af[mi][1], af[mi][2], af[mi][3], addr);
            }
            {
                uint32_t addr = bBase + (uint32_t)((bRow * 72 + kb) * 2);
                LDSM_X4(bh[0], bh[1], bh[2], bh[3], addr);
            }
#pragma unroll
            for (int mi = 0; mi < 3; mi++)
#pragma unroll
                for (int nj = 0; nj < 2; nj++)
                    MMA16816(acc[mi][nj], af[mi], bh[nj * 2], bh[nj * 2 + 1]);
        }
    }
    const bool doT = (EPI == 0) && (n0 < 2 * H2);
#pragma unroll
    for (int mi = 0; mi < 3; mi++)
#pragma unroll
        for (int nj = 0; nj < 2; nj++)
#pragma unroll
            for (int r = 0; r < 4; r++) {
                int m = wm * 48 + mi * 16 + (lane >> 2) + ((r >> 1) * 8);
                int gl = wn * 16 + nj * 8 + (lane & 3) * 2 + (r & 1);
                int gn = n0 + gl;
                float v = acc[mi][nj][r] + bias[gn];
                if (EPI == 0) { if (gn < H2) v *= (1.0f / 96.0f); }
                if (EPI == 1) v = 1.0f / (1.0f + expf(-v));
                out[(size_t)m * ldo + gn] = v;
                if (doT) {
                    __nv_bfloat16 hi = __float2bfloat16(v);
                    sT[gl * 192 + m] = hi;
                    sT[gl * 192 + 96 + m] = __float2bfloat16(v - __bfloat162float(hi));
                }
            }
    if (doT) {
        __syncthreads();
        __nv_bfloat16* dstT = (__nv_bfloat16*)((n0 < H2) ? kT_u16 : qT_u16);
        int cb = (n0 < H2) ? n0 : (n0 - H2);
        for (int e = tid; e < 64 * 24; e += 256) {
            int row = e / 24, g = e % 24;
            *(uint4*)(dstT + (size_t)(cb + row) * 192 + g * 8) = *(uint4*)(sT + row * 192 + g * 8);
        }
    }
}

// ======== Variant B: HMMA NT GEMM, pre-split bf16 B [N, 192], up to 2 K-segments ====
// EPI 2: n (+ fused AT transpose-split), EPI 3: h = o * acc / denom
template <int EPI>
__global__ __launch_bounds__(256, 2)
void hmma_preB(const unsigned short* __restrict__ Asp_u16, int lda,
               const unsigned short* __restrict__ B1_u16,
               const unsigned short* __restrict__ B2_u16,
               int nseg,
               const float* __restrict__ omat,
               const int* __restrict__ denomBits,
               float* __restrict__ out, int ldo,
               unsigned short* __restrict__ AT_u16) {
    const __nv_bfloat16* Asp = (const __nv_bfloat16*)Asp_u16;
    extern __shared__ __nv_bfloat16 dsm[];
    __nv_bfloat16* sA = dsm;             // [96][200]
    __nv_bfloat16* sB = dsm + 96 * 200;  // [64][200]
    int tid = threadIdx.x, warp = tid >> 5, lane = tid & 31;
    int n0 = blockIdx.x * 64;
    int wm = warp & 1, wn = warp >> 1;
    float acc[3][2][4] = {};

#pragma unroll 1
    for (int s = 0; s < nseg; s++) {
        const __nv_bfloat16* Bseg =
            (s == 0) ? (const __nv_bfloat16*)B1_u16 : (const __nv_bfloat16*)B2_u16;
        __syncthreads();
        for (int e = tid; e < 96 * 24; e += 256) {
            int r = e / 24, g = e % 24;
            *(uint4*)(sA + r * 200 + g * 8) =
                *(const uint4*)(Asp + (size_t)r * lda + s * 192 + g * 8);
        }
        for (int e = tid; e < 64 * 24; e += 256) {
            int r = e / 24, g = e % 24;
            *(uint4*)(sB + r * 200 + g * 8) =
                *(const uint4*)(Bseg + (size_t)(n0 + r) * 192 + g * 8);
        }
        __syncthreads();
        uint32_t aBase = smem_u32(sA), bBase = smem_u32(sB);
        int aRow = wm * 48 + (lane & 15), aCol = (lane >> 4) << 3;
        int bRow = wn * 16 + (lane & 7) + ((lane >> 4) << 3);
        int bCol = ((lane >> 3) & 1) << 3;
        // merged passes: A_hi x (B_hi, B_lo)
#pragma unroll
        for (int ks = 0; ks < 6; ks++) {
            int ka = ks * 16 + aCol, kb = ks * 16 + bCol;
            uint32_t af[3][4], bh[4], bl[4];
#pragma unroll
            for (int mi = 0; mi < 3; mi++) {
                uint32_t addr = aBase + (uint32_t)(((aRow + mi * 16) * 200 + ka) * 2);
                LDSM_X4(af[mi][0], af[mi][1], af[mi][2], af[mi][3], addr);
            }
            {
                uint32_t addr = bBase + (uint32_t)((bRow * 200 + kb) * 2);
                LDSM_X4(bh[0], bh[1], bh[2], bh[3], addr);
                addr = bBase + (uint32_t)((bRow * 200 + kb + 96) * 2);
                LDSM_X4(bl[0], bl[1], bl[2], bl[3], addr);
            }
#pragma unroll
            for (int mi = 0; mi < 3; mi++)
#pragma unroll
                for (int nj = 0; nj < 2; nj++) {
                    MMA16816(acc[mi][nj], af[mi], bh[nj * 2], bh[nj * 2 + 1]);
                    MMA16816(acc[mi][nj], af[mi], bl[nj * 2], bl[nj * 2 + 1]);
                }
        }
        // pass 2: A_lo x B_hi
#pragma unroll
        for (int ks = 0; ks < 6; ks++) {
            int ka = 96 + ks * 16 + aCol, kb = ks * 16 + bCol;
            uint32_t af[3][4], bh[4];
#pragma unroll
            for (int mi = 0; mi < 3; mi++) {
                uint32_t addr = aBase + (uint32_t)(((aRow + mi * 16) * 200 + ka) * 2);
                LDSM_X4(af[mi][0], af[mi][1], af[mi][2], af[mi][3], addr);
            }
            {
                uint32_t addr = bBase + (uint32_t)((bRow * 200 + kb) * 2);
                LDSM_X4(bh[0], bh[1], bh[2], bh[3], addr);
            }
#pragma unroll
            for (int mi = 0; mi < 3; mi++)
#pragma unroll
                for (int nj = 0; nj < 2; nj++)
                    MMA16816(acc[mi][nj], af[mi], bh[nj * 2], bh[nj * 2 + 1]);
        }
    }
    if (EPI == 2) __syncthreads();   // before reusing sA as staging
#pragma unroll
    for (int mi = 0; mi < 3; mi++)
#pragma unroll
        for (int nj = 0; nj < 2; nj++)
#pragma unroll
            for (int r = 0; r < 4; r++) {
                int m = wm * 48 + mi * 16 + (lane >> 2) + ((r >> 1) * 8);
                int gl = wn * 16 + nj * 8 + (lane & 3) * 2 + (r & 1);
                int gn = n0 + gl;
                float v = acc[mi][nj][r];
                if (EPI == 3)
                    v = omat[(size_t)m * H2 + gn] * v / __int_as_float(denomBits[gn]);
                out[(size_t)m * ldo + gn] = v;
                if (EPI == 2) {
                    __nv_bfloat16 hi = __float2bfloat16(v);
                    sA[gl * 192 + m] = hi;
                    sA[gl * 192 + 96 + m] = __float2bfloat16(v - __bfloat162float(hi));
                }
            }
    if (EPI == 2) {
        __syncthreads();
        __nv_bfloat16* AT = (__nv_bfloat16*)AT_u16;
        for (int e = tid; e < 64 * 24; e += 256) {
            int row = e / 24, g = e % 24;
            *(uint4*)(AT + (size_t)(n0 + row) * 192 + g * 8) = *(uint4*)(sA + row * 192 + g * 8);
        }
    }
}

// ================= HMMA denom: A-resident, 6 B tiles per CTA =================
#define SMN_LD 200

__global__ __launch_bounds__(256, 2)
void denom_mma_kernel(const unsigned short* __restrict__ AT,
                      const unsigned short* __restrict__ BT,
                      int* __restrict__ denom) {
    extern __shared__ __align__(16) unsigned short sm[];
    unsigned short* sA = sm;
    unsigned short* sB = sm + 128 * SMN_LD;
    int tid = threadIdx.x;
    int r0 = blockIdx.x * 128;
    int cbase = blockIdx.y * 768;   // 6 tiles of 128

    // A tile loaded once per CTA
    for (int e = tid; e < 128 * 24; e += 256) {
        int row = e / 24, c8 = (e % 24) * 8;
        *(float4*)(sA + row * SMN_LD + c8) = *(const float4*)(AT + (size_t)(r0 + row) * 192 + c8);
    }

    int warp = tid >> 5, lane = tid & 31;
    int wm = warp & 1, wn = warp >> 1;
    uint32_t aBase = smem_u32(sA);
    uint32_t bBase = smem_u32(sB);

    int aRow = wm * 64 + (lane & 15);
    int aColL = (lane >> 4) << 3;
    int bRow = wn * 32 + (lane & 7) + ((lane >> 4) << 3);
    int bColL = ((lane >> 3) & 1) << 3;

    float mx[4][2];   // row-max accumulators (mi x {m0,m1}), persist across tiles
#pragma unroll
    for (int mi = 0; mi < 4; mi++) { mx[mi][0] = 0.f; mx[mi][1] = 0.f; }

#pragma unroll 1
    for (int t = 0; t < 6; t++) {
        __syncthreads();   // prev tile's MMAs done reading sB (and first-iter A store drain)
        for (int e = tid; e < 128 * 24; e += 256) {
            int row = e / 24, c8 = (e % 24) * 8;
            *(float4*)(sB + row * SMN_LD + c8) =
                *(const float4*)(BT + (size_t)(cbase + t * 128 + row) * 192 + c8);
        }
        __syncthreads();

        float acc[4][4][4];
#pragma unroll
        for (int mi = 0; mi < 4; mi++)
#pragma unroll
            for (int nj = 0; nj < 4; nj++)
#pragma unroll
                for (int r = 0; r < 4; r++) acc[mi][nj][r] = 0.f;

        // merged passes: A_hi x (B_hi, B_lo)
#pragma unroll 1
        for (int ks = 0; ks < 6; ks++) {
            int ka = ks * 16 + aColL;
            int kb = ks * 16 + bColL;
            uint32_t af[4][4], bh[2][4], bl[2][4];
#pragma unroll
            for (int mi = 0; mi < 4; mi++) {
                uint32_t addr = aBase + (uint32_t)(((aRow + mi * 16) * SMN_LD + ka) * 2);
                LDSM_X4(af[mi][0], af[mi][1], af[mi][2], af[mi][3], addr);
            }
#pragma unroll
            for (int nj2 = 0; nj2 < 2; nj2++) {
                uint32_t addr = bBase + (uint32_t)(((bRow + nj2 * 16) * SMN_LD + kb) * 2);
                LDSM_X4(bh[nj2][0], bh[nj2][1], bh[nj2][2], bh[nj2][3], addr);
                addr = bBase + (uint32_t)(((bRow + nj2 * 16) * SMN_LD + kb + 96) * 2);
                LDSM_X4(bl[nj2][0], bl[nj2][1], bl[nj2][2], bl[nj2][3], addr);
            }
#pragma unroll
            for (int mi = 0; mi < 4; mi++)
#pragma unroll
                for (int nj = 0; nj < 4; nj++) {
                    MMA16816(acc[mi][nj], af[mi], bh[nj >> 1][(nj & 1) * 2],
                             bh[nj >> 1][(nj & 1) * 2 + 1]);
                    MMA16816(acc[mi][nj], af[mi], bl[nj >> 1][(nj & 1) * 2],
                             bl[nj >> 1][(nj & 1) * 2 + 1]);
                }
        }
        // pass 2: A_lo x B_hi
#pragma unroll 1
        for (int ks = 0; ks < 6; ks++) {
            int ka = 96 + ks * 16 + aColL;
            int kb = ks * 16 + bColL;
            uint32_t af[4][4], bh[2][4];
#pragma unroll
            for (int mi = 0; mi < 4; mi++) {
                uint32_t addr = aBase + (uint32_t)(((aRow + mi * 16) * SMN_LD + ka) * 2);
                LDSM_X4(af[mi][0], af[mi][1], af[mi][2], af[mi][3], addr);
            }
#pragma unroll
            for (int nj2 = 0; nj2 < 2; nj2++) {
                uint32_t addr = bBase + (uint32_t)(((bRow + nj2 * 16) * SMN_LD + kb) * 2);
                LDSM_X4(bh[nj2][0], bh[nj2][1], bh[nj2][2], bh[nj2][3], addr);
            }
#pragma unroll
            for (int mi = 0; mi < 4; mi++)
#pragma unroll
                for (int nj = 0; nj < 4; nj++)
                    MMA16816(acc[mi][nj], af[mi], bh[nj >> 1][(nj & 1) * 2],
                             bh[nj >> 1][(nj & 1) * 2 + 1]);
        }

        // fold tile into row-max accumulators
#pragma unroll
        for (int mi = 0; mi < 4; mi++) {
#pragma unroll
            for (int nj = 0; nj < 4; nj++) {
                mx[mi][0] = fmaxf(mx[mi][0], fmaxf(fabsf(acc[mi][nj][0]), fabsf(acc[mi][nj][1])));
                mx[mi][1] = fmaxf(mx[mi][1], fmaxf(fabsf(acc[mi][nj][2]), fabsf(acc[mi][nj][3])));
            }
        }
    }

    // final: quad shfl reduce + one atomicMax per row
#pragma unroll
    for (int mi = 0; mi < 4; mi++) {
        float m0 = mx[mi][0], m1 = mx[mi][1];
        m0 = fmaxf(m0, __shfl_xor_sync(0xffffffffu, m0, 1));
        m0 = fmaxf(m0, __shfl_xor_sync(0xffffffffu, m0, 2));
        m1 = fmaxf(m1, __shfl_xor_sync(0xffffffffu, m1, 1));
        m1 = fmaxf(m1, __shfl_xor_sync(0xffffffffu, m1, 2));
        if ((lane & 3) == 0) {
            int rbase = r0 + wm * 64 + mi * 16 + (lane >> 2);
            atomicMax(&denom[rbase], __float_as_int(m0));
            atomicMax(&denom[rbase + 8], __float_as_int(m1));
        }
    }
}

// ---------------- v @ k^T : deterministic split-K (16 chunks of 576) ----------------
__global__ __launch_bounds__(256)
void vkt_part_kernel(const float* __restrict__ kqv, float* __restrict__ part) {
    const float* V  = kqv + 2 * H2;
    const float* Km = kqv;
    __shared__ float As[32][17];
    __shared__ float Bs[32][17];
    int tid = threadIdx.x, tx = tid & 15, ty = tid >> 4;
    int m0 = blockIdx.x * 32, n0 = blockIdx.y * 32;
    int kbase = blockIdx.z * 576;
    float a00 = 0, a01 = 0, a10 = 0, a11 = 0;
    for (int k0 = 0; k0 < 576; k0 += 16) {
        for (int e = tid; e < 32 * 16; e += 256) {
            int m = e >> 4, k = e & 15;
            As[m][k] = V[(size_t)(m0 + m) * KQVN + kbase + k0 + k];
            Bs[m][k] = Km[(size_t)(n0 + m) * KQVN + kbase + k0 + k];
        }
        __syncthreads();
#pragma unroll
        for (int kk = 0; kk < 16; kk++) {
            float av0 = As[ty][kk],      av1 = As[ty + 16][kk];
            float bv0 = Bs[tx][kk],      bv1 = Bs[tx + 16][kk];
            a00 += av0 * bv0; a01 += av0 * bv1;
            a10 += av1 * bv0; a11 += av1 * bv1;
        }
        __syncthreads();
    }
    float* p = part + blockIdx.z * (Hs * Hs);
    p[(m0 + ty) * Hs + (n0 + tx)]           = a00;
    p[(m0 + ty) * Hs + (n0 + tx + 16)]      = a01;
    p[(m0 + ty + 16) * Hs + (n0 + tx)]      = a10;
    p[(m0 + ty + 16) * Hs + (n0 + tx + 16)] = a11;
}

__global__ void vkt_reduce_kernel(const float* __restrict__ part, float* __restrict__ vkt) {
    int idx = blockIdx.x * blockDim.x + threadIdx.x;
    if (idx < Hs * Hs) {
        float s = 0.f;
#pragma unroll
        for (int c = 0; c < 16; c++) s += part[c * (Hs * Hs) + idx];
        vkt[idx] = s;
    }
}

// ---------------- C = f @ C_prev + i @ vkT   (96x96), + split ----------------
__global__ void c_kernel(const float* __restrict__ f, const float* __restrict__ i_,
                         const float* __restrict__ C_prev, const float* __restrict__ vkt,
                         float* __restrict__ outC, unsigned short* __restrict__ Cs_u16) {
    __shared__ float fs[Hs], is[Hs];
    int b = blockIdx.x, n = threadIdx.x;
    fs[n] = f[b * Hs + n];
    is[n] = i_[b * Hs + n];
    __syncthreads();
    float acc = 0.f;
    for (int h = 0; h < Hs; h++)
        acc += fs[h] * C_prev[h * Hs + n] + is[h] * vkt[h * Hs + n];
    outC[b * Hs + n] = acc;
    __nv_bfloat16* Cs = (__nv_bfloat16*)Cs_u16;
    __nv_bfloat16 hi = __float2bfloat16(acc);
    Cs[b * 192 + n] = hi;
    Cs[b * 192 + 96 + n] = __float2bfloat16(acc - __bfloat162float(hi));
}

// ---------------- launch ----------------
extern "C" void kernel_launch(void* const* d_in, const int* in_sizes, int n_in,
                              void* d_out, int out_size) {
    const float* x      = (const float*)d_in[0];
    const float* h_prev = (const float*)d_in[1];
    const float* C_prev = (const float*)d_in[2];
    const float* n_prev = (const float*)d_in[3];
    const float* wix_w  = (const float*)d_in[4];
    const float* wix_b  = (const float*)d_in[5];
    const float* wfx_w  = (const float*)d_in[6];
    const float* wfx_b  = (const float*)d_in[7];
    const float* Wox_w  = (const float*)d_in[8];
    const float* Wox_b  = (const float*)d_in[9];
    const float* Wkqv_w = (const float*)d_in[10];
    const float* Wkqv_b = (const float*)d_in[11];

    float* out   = (float*)d_out;
    float* out_h = out;                       // [96, 9216]
    float* out_C = out + Bsz * H2;            // [96, 96]
    float* out_n = out_C + Bsz * Hs;          // [96, 9216]

    float *p_i, *p_f, *p_o, *p_kqv, *p_part, *p_vkt;
    int* p_denom;
    unsigned short *p_AT, *p_BT, *p_npT, *p_kT, *p_xs, *p_hps, *p_fis, *p_Cs;
    cudaGetSymbolAddress((void**)&p_i,     g_i);
    cudaGetSymbolAddress((void**)&p_f,     g_f);
    cudaGetSymbolAddress((void**)&p_o,     g_o);
    cudaGetSymbolAddress((void**)&p_kqv,   g_kqv);
    cudaGetSymbolAddress((void**)&p_part,  g_vkT_part);
    cudaGetSymbolAddress((void**)&p_vkt,   g_vkT);
    cudaGetSymbolAddress((void**)&p_denom, g_denom);
    cudaGetSymbolAddress((void**)&p_AT,    g_AT);
    cudaGetSymbolAddress((void**)&p_BT,    g_BT);
    cudaGetSymbolAddress((void**)&p_npT,   g_npT);
    cudaGetSymbolAddress((void**)&p_kT,    g_kT);
    cudaGetSymbolAddress((void**)&p_xs,    g_xs);
    cudaGetSymbolAddress((void**)&p_hps,   g_hps);
    cudaGetSymbolAddress((void**)&p_fis,   g_fis);
    cudaGetSymbolAddress((void**)&p_Cs,    g_Cs);

    const int DENOM_SMEM = 2 * 128 * SMN_LD * 2;                 // 102400
    const int PREB_SMEM  = (96 + 64) * 200 * 2;                  // 64000
    const int CONV_SMEM  = (96 * 72 + 64 * 72 + 64 * 192) * 2;   // 47616
    const int CONV1_SMEM = (96 * 72 + 64 * 72) * 2;              // 23040
    cudaFuncSetAttribute(denom_mma_kernel,
                         cudaFuncAttributeMaxDynamicSharedMemorySize, DENOM_SMEM);
    cudaFuncSetAttribute(hmma_preB<2>,
                         cudaFuncAttributeMaxDynamicSharedMemorySize, PREB_SMEM);
    cudaFuncSetAttribute(hmma_preB<3>,
                         cudaFuncAttributeMaxDynamicSharedMemorySize, PREB_SMEM);
    cudaFuncSetAttribute(hmma_convA<0, Ds>,
                         cudaFuncAttributeMaxDynamicSharedMemorySize, CONV_SMEM);
    cudaFuncSetAttribute(hmma_convA<1, Hs>,
                         cudaFuncAttributeMaxDynamicSharedMemorySize, CONV1_SMEM);

    // x/h_prev splits + denom zero (one launch)
    split_misc<<<360, 256>>>(x, h_prev, p_xs, p_hps, p_denom);

    // n_prev^T split
    prep_splitT<<<dim3(H2 / 64, 3), 256>>>(n_prev, H2, p_npT);

    // i, f gates + split (one launch)
    gates_kernel<<<2304, 256>>>(x, h_prev, wix_w, wix_b, wfx_w, wfx_b, p_i, p_f, p_fis);

    // kqv = x @ Wkqv^T + b (HMMA, occ-3 N64 tiles) + fused kT/qT transpose-splits
    hmma_convA<0, Ds><<<KQVN / 64, 256, CONV_SMEM>>>(p_xs, Wkqv_w, Wkqv_b, p_kqv, KQVN,
                                                     p_kT, p_BT);

    // o = sigmoid(h_prev @ Wox^T + b)
    hmma_convA<1, Hs><<<H2 / 64, 256, CONV1_SMEM>>>(p_hps, Wox_w, Wox_b, p_o, H2,
                                                    nullptr, nullptr);

    // n = f @ n_prev + i @ k  (HMMA) + fused AT transpose-split
    hmma_preB<2><<<H2 / 64, 256, PREB_SMEM>>>(p_fis, 384, p_npT, p_kT, 2,
                                              nullptr, nullptr, out_n, H2, p_AT);

    // vkT = v @ k^T
    vkt_part_kernel<<<dim3(3, 3, 16), 256>>>(p_kqv, p_part);
    vkt_reduce_kernel<<<36, 256>>>(p_part, p_vkt);

    // C = f @ C_prev + i @ vkT (+ split)
    c_kernel<<<Bsz, Hs>>>(p_f, p_i, C_prev, p_vkt, out_C, p_Cs);

    // denom = max_c |n^T q|  (A-resident, 6 B tiles per CTA)
    denom_mma_kernel<<<dim3(72, 12), 256, DENOM_SMEM>>>(p_AT, p_BT, p_denom);

    // h = o * (C @ q) / denom
    hmma_preB<3><<<H2 / 64, 256, PREB_SMEM>>>(p_Cs, 192, p_BT, nullptr, 1,
                                              p_o, p_denom, out_h, H2, nullptr);
}